// round 5
// baseline (speedup 1.0000x reference)
#include <cuda_runtime.h>
#include <cuda_fp16.h>
#include <math.h>

// ---------------------------------------------------------------------------
// Problem dims
// ---------------------------------------------------------------------------
#define D_    2048
#define V_    2048
#define LSEQ  512
#define LP1   513
#define T_    65
#define G4    8192

#define NBLK  148
#define NT    1024
#define NW    32

#define SROWS 54              // SMEM-resident gate rows per block (148*54 = 7992)
#define LEFT  200             // leftover gate rows 7992..8191 (kept in L2 fp16)
#define XROWS (LEFT + V_)     // 2248 rows in g_w16: leftover gates + all d rows

// dynamic smem layout (bytes)
#define OFF_H     (SROWS * D_ * 2)          // 221184: h[2048] floats
#define OFF_RED   (OFF_H + D_ * 4)          // 229376: red[32]
#define SMEM_BYTES (OFF_RED + 128)          // 229504

// ---------------------------------------------------------------------------
// Device scratch
// ---------------------------------------------------------------------------
__device__ __half g_w16[(size_t)XROWS * D_];   // 9.2 MB fp16 (leftover gates + Wd)
__device__ float g_enc[LP1 * V_];              // enc_proj
__device__ float g_gates[2][G4];               // double-buffered gates
__device__ float g_dall[T_][V_];               // d_t for all steps
__device__ unsigned g_cnt;
__device__ unsigned g_gen;

// ---------------------------------------------------------------------------
// Acquire/release grid barrier (all 148 blocks co-resident)
// ---------------------------------------------------------------------------
__device__ __forceinline__ unsigned ld_acq(const unsigned* p) {
    unsigned v;
    asm volatile("ld.acquire.gpu.global.u32 %0, [%1];" : "=r"(v) : "l"(p) : "memory");
    return v;
}
__device__ __forceinline__ void st_rel(unsigned* p, unsigned v) {
    asm volatile("st.release.gpu.global.u32 [%0], %1;" :: "l"(p), "r"(v) : "memory");
}
__device__ __forceinline__ unsigned atom_add_rel(unsigned* p, unsigned v) {
    unsigned old;
    asm volatile("atom.release.gpu.global.add.u32 %0, [%1], %2;"
                 : "=r"(old) : "l"(p), "r"(v) : "memory");
    return old;
}
__device__ __forceinline__ void gridbar() {
    __syncthreads();
    if (threadIdx.x == 0) {
        unsigned g = ld_acq(&g_gen);
        if (atom_add_rel(&g_cnt, 1u) == NBLK - 1u) {
            atomicExch(&g_cnt, 0u);
            st_rel(&g_gen, g + 1u);
        } else {
            while (ld_acq(&g_gen) == g) { }
        }
    }
    __syncthreads();
}

// ---------------------------------------------------------------------------
// Branchless rational tanh (Eigen 13/6) + Newton reciprocal (no MUFU)
// ---------------------------------------------------------------------------
__device__ __forceinline__ float fast_tanh(float x) {
    float xc = fminf(fmaxf(x, -7.90531110763549805f), 7.90531110763549805f);
    float x2 = xc * xc;
    float p = -2.76076847742355e-16f;
    p = fmaf(p, x2, 2.00018790482477e-13f);
    p = fmaf(p, x2, -8.60467152213735e-11f);
    p = fmaf(p, x2, 5.12229709037114e-08f);
    p = fmaf(p, x2, 1.48572235717979e-05f);
    p = fmaf(p, x2, 6.37261928875436e-04f);
    p = fmaf(p, x2, 4.89352455891786e-03f);
    p *= xc;
    float q = 1.19825839466702e-06f;
    q = fmaf(q, x2, 1.18534705686654e-04f);
    q = fmaf(q, x2, 2.26843463243900e-03f);
    q = fmaf(q, x2, 4.89352518554385e-03f);
    float r = __uint_as_float(0x7EF311C3u - __float_as_uint(q));
    r = r * fmaf(-q, r, 2.0f);
    r = r * fmaf(-q, r, 2.0f);
    r = r * fmaf(-q, r, 2.0f);
    r = r * fmaf(-q, r, 2.0f);
    return p * r;
}
__device__ __forceinline__ float fast_sigmoid(float x) {
    return fmaf(0.5f, fast_tanh(0.5f * x), 0.5f);
}

// fp16 dot8: uint4 = 8 halves vs 8 floats
__device__ __forceinline__ float dot8(uint4 u, float4 ha, float4 hb, float acc) {
    float2 f0 = __half22float2(*(__half2*)&u.x);
    float2 f1 = __half22float2(*(__half2*)&u.y);
    float2 f2 = __half22float2(*(__half2*)&u.z);
    float2 f3 = __half22float2(*(__half2*)&u.w);
    acc = fmaf(f0.x, ha.x, acc);
    acc = fmaf(f0.y, ha.y, acc);
    acc = fmaf(f1.x, ha.z, acc);
    acc = fmaf(f1.y, ha.w, acc);
    acc = fmaf(f2.x, hb.x, acc);
    acc = fmaf(f2.y, hb.y, acc);
    acc = fmaf(f3.x, hb.z, acc);
    acc = fmaf(f3.y, hb.w, acc);
    return acc;
}

// mma.sync m16n8k16 row.col f32.f16.f16.f32
__device__ __forceinline__ void mma16816(float* c, const unsigned* a, const unsigned* b) {
    asm volatile(
        "mma.sync.aligned.m16n8k16.row.col.f32.f16.f16.f32 "
        "{%0,%1,%2,%3}, {%4,%5,%6,%7}, {%8,%9}, {%0,%1,%2,%3};"
        : "+f"(c[0]), "+f"(c[1]), "+f"(c[2]), "+f"(c[3])
        : "r"(a[0]), "r"(a[1]), "r"(a[2]), "r"(a[3]), "r"(b[0]), "r"(b[1]));
}

#define KS 40                                // half stride per smem GEMM tile row

__global__ void __launch_bounds__(NT, 1)
decoder_kernel(const float* __restrict__ initial_state,
               const float* __restrict__ enc_states,
               const float* __restrict__ seq_points,
               const int*   __restrict__ positions,
               const float* __restrict__ W_ih,
               const float* __restrict__ W_hh,
               const float* __restrict__ b_ih,
               const float* __restrict__ b_hh,
               const float* __restrict__ We_w,
               const float* __restrict__ We_b,
               const float* __restrict__ Wd_w,
               const float* __restrict__ Wd_b,
               const float* __restrict__ v_w,
               const float* __restrict__ v_b,
               float* __restrict__ out_logits,
               float* __restrict__ out_hs,
               float* __restrict__ out_losses)
{
    extern __shared__ __align__(16) char dynsm[];
    __half* wsm = (__half*)dynsm;                      // stage 1 weights
    float*  hsm = (float*)(dynsm + OFF_H);             // h state
    float*  red = (float*)(dynsm + OFF_RED);           // stage-3 reductions

    const int tid  = threadIdx.x;
    const int wid  = tid >> 5;
    const int lane = tid & 31;
    const int b    = blockIdx.x;

    // =======================================================================
    // Phase G: enc_proj GEMM on tensor cores (blocks 0..79, one 128x128 tile)
    // =======================================================================
    if (b < 80) {
        __half* ga = (__half*)dynsm;                   // [128][KS]
        __half* gb = ga + 128 * KS;
        const int l0 = (b / 16) * 128;
        const int v0 = (b % 16) * 128;
        const int warpM = wid >> 3;
        const int warpN = wid & 7;
        const int g  = lane >> 2;
        const int t2 = (lane & 3) * 2;
        const int ldrow = tid >> 3;
        const int ldk   = (tid & 7) * 4;

        float c[2][2][4];
        #pragma unroll
        for (int m = 0; m < 2; ++m)
            #pragma unroll
            for (int n = 0; n < 2; ++n)
                #pragma unroll
                for (int q = 0; q < 4; ++q) c[m][n][q] = 0.f;

        for (int k0 = 0; k0 < D_; k0 += 32) {
            int gl = l0 + ldrow; if (gl > 512) gl = 512;
            float4 av = *(const float4*)&enc_states[(size_t)gl * D_ + k0 + ldk];
            float4 bv = *(const float4*)&We_w[(size_t)(v0 + ldrow) * D_ + k0 + ldk];
            __syncthreads();
            *(__half2*)&ga[ldrow * KS + ldk]     = __floats2half2_rn(av.x, av.y);
            *(__half2*)&ga[ldrow * KS + ldk + 2] = __floats2half2_rn(av.z, av.w);
            *(__half2*)&gb[ldrow * KS + ldk]     = __floats2half2_rn(bv.x, bv.y);
            *(__half2*)&gb[ldrow * KS + ldk + 2] = __floats2half2_rn(bv.z, bv.w);
            __syncthreads();

            #pragma unroll
            for (int ks = 0; ks < 2; ++ks) {
                const int kb = ks * 16;
                unsigned a[2][4], bb[2][2];
                #pragma unroll
                for (int m = 0; m < 2; ++m) {
                    int ar = warpM * 32 + m * 16;
                    a[m][0] = *(const unsigned*)&ga[(ar + g) * KS + kb + t2];
                    a[m][1] = *(const unsigned*)&ga[(ar + g + 8) * KS + kb + t2];
                    a[m][2] = *(const unsigned*)&ga[(ar + g) * KS + kb + t2 + 8];
                    a[m][3] = *(const unsigned*)&ga[(ar + g + 8) * KS + kb + t2 + 8];
                }
                #pragma unroll
                for (int n = 0; n < 2; ++n) {
                    int br = warpN * 16 + n * 8;
                    bb[n][0] = *(const unsigned*)&gb[(br + g) * KS + kb + t2];
                    bb[n][1] = *(const unsigned*)&gb[(br + g) * KS + kb + t2 + 8];
                }
                #pragma unroll
                for (int m = 0; m < 2; ++m)
                    #pragma unroll
                    for (int n = 0; n < 2; ++n)
                        mma16816(c[m][n], a[m], bb[n]);
            }
        }

        #pragma unroll
        for (int m = 0; m < 2; ++m) {
            #pragma unroll
            for (int n = 0; n < 2; ++n) {
                int lrow = l0 + warpM * 32 + m * 16 + g;
                int vcol = v0 + warpN * 16 + n * 8 + t2;
                if (lrow < LP1) {
                    g_enc[(size_t)lrow * V_ + vcol]     = c[m][n][0] + We_b[vcol];
                    g_enc[(size_t)lrow * V_ + vcol + 1] = c[m][n][1] + We_b[vcol + 1];
                }
                if (lrow + 8 < LP1) {
                    g_enc[(size_t)(lrow + 8) * V_ + vcol]     = c[m][n][2] + We_b[vcol];
                    g_enc[(size_t)(lrow + 8) * V_ + vcol + 1] = c[m][n][3] + We_b[vcol + 1];
                }
            }
        }
        __syncthreads();          // done with GEMM tiles before smem reuse
    }

    // =======================================================================
    // Prologue A: load this block's 54 gate rows into SMEM as fp16
    // =======================================================================
    {
        const float4* src = (const float4*)(W_hh + (size_t)b * SROWS * D_);
        uint2* dst = (uint2*)wsm;
        const int n4 = SROWS * D_ / 4;                 // 27648
        for (int i = tid; i < n4; i += NT) {
            float4 v = src[i];
            __half2 h01 = __floats2half2_rn(v.x, v.y);
            __half2 h23 = __floats2half2_rn(v.z, v.w);
            uint2 pk;
            pk.x = *(unsigned*)&h01;
            pk.y = *(unsigned*)&h23;
            dst[i] = pk;
        }
    }
    // Prologue B: convert leftover gate rows + Wd_w rows to g_w16 (grid-strided)
    {
        const int NG4 = LEFT * (D_ / 4);               // 102400
        const int NT4 = XROWS * (D_ / 4);              // 1150976
        const float4* lg = (const float4*)(W_hh + (size_t)(G4 - LEFT) * D_);
        uint2* dst = (uint2*)g_w16;
        for (int i = b * NT + tid; i < NT4; i += NBLK * NT) {
            float4 v = (i < NG4) ? lg[i] : ((const float4*)Wd_w)[i - NG4];
            __half2 h01 = __floats2half2_rn(v.x, v.y);
            __half2 h23 = __floats2half2_rn(v.z, v.w);
            uint2 pk;
            pk.x = *(unsigned*)&h01;
            pk.y = *(unsigned*)&h23;
            dst[i] = pk;
        }
    }

    // =======================================================================
    // Stage 1 setup: row ownership
    //   warps 0..21: 2 SMEM rows; warps 22..31: 1 SMEM row
    //   extra (L2 fp16) row: leftover gate (w16/w17) or d row (w18..31)
    // =======================================================================
    const int  s0   = (wid < 22) ? 2 * wid : 44 + (wid - 22);
    const bool has1 = (wid < 22);
    const int  s1   = 2 * wid + 1;
    const int  r0g  = b * SROWS + s0;
    const int  r1g  = b * SROWS + s1;

    bool ex_gate = false;
    int  ex_r = -1, ex_idx = -1;                       // ex_r: gate row or d index
    if (wid == 17)                 { ex_gate = true;  ex_r = (G4 - LEFT) + b; ex_idx = b; }
    else if (wid == 16 && b < 52)  { ex_gate = true;  ex_r = (G4 - LEFT) + 148 + b; ex_idx = 148 + b; }
    else if (wid >= 22)            { ex_r = b * 10 + (wid - 22);        ex_idx = LEFT + ex_r; }
    else if (wid >= 19)            { ex_r = 1480 + b * 3 + (wid - 19);  ex_idx = LEFT + ex_r; }
    else if (wid == 18 && b < 124) { ex_r = 1924 + b;                   ex_idx = LEFT + ex_r; }
    const bool hasex = (ex_idx >= 0);
    const uint4* exw = (const uint4*)(g_w16 + (size_t)(hasex ? ex_idx : 0) * D_);
    const uint4* w0  = (const uint4*)(wsm + (size_t)s0 * D_);
    const uint4* w1  = (const uint4*)(wsm + (size_t)s1 * D_);

    // init state (h in SMEM, c in regs: j0 = tid, j1 = tid + NT)
    float c0 = 0.f, c1 = 0.f;
    hsm[tid]      = initial_state[tid];
    hsm[tid + NT] = initial_state[tid + NT];
    gridbar();     // weights converted + h ready everywhere

    // =======================================================================
    // Stage 1: 66 iterations, one grid barrier each
    // =======================================================================
    for (int t = 0; t <= T_; ++t) {
        const bool dog  = (t < T_);
        const bool doex = hasex && (ex_gate ? dog : (t > 0));

        const float4* h4 = (const float4*)hsm;
        float a0 = 0.f, a1 = 0.f, a2 = 0.f;

        #pragma unroll 4
        for (int k8 = lane; k8 < 256; k8 += 32) {
            float4 ha = h4[2 * k8];
            float4 hb = h4[2 * k8 + 1];
            if (doex) a2 = dot8(__ldcg(exw + k8), ha, hb, a2);
            if (dog) {
                a0 = dot8(w0[k8], ha, hb, a0);
                if (has1) a1 = dot8(w1[k8], ha, hb, a1);
            }
        }
        #pragma unroll
        for (int off = 16; off > 0; off >>= 1) {
            a0 += __shfl_down_sync(0xffffffffu, a0, off);
            a1 += __shfl_down_sync(0xffffffffu, a1, off);
            a2 += __shfl_down_sync(0xffffffffu, a2, off);
        }

        if (lane == 0) {
            float x0 = 0.f, x1 = 0.f, x2 = 1.f;
            if (t >= 1 && t <= 64) {
                int pos = positions[t - 1];
                x0 = seq_points[pos * 3 + 0];
                x1 = seq_points[pos * 3 + 1];
                x2 = seq_points[pos * 3 + 2];
            }
            if (dog) {
                float e0 = b_ih[r0g] + b_hh[r0g]
                         + W_ih[r0g * 3 + 0] * x0
                         + W_ih[r0g * 3 + 1] * x1
                         + W_ih[r0g * 3 + 2] * x2;
                __stcg(&g_gates[t & 1][r0g], a0 + e0);
                if (has1) {
                    float e1 = b_ih[r1g] + b_hh[r1g]
                             + W_ih[r1g * 3 + 0] * x0
                             + W_ih[r1g * 3 + 1] * x1
                             + W_ih[r1g * 3 + 2] * x2;
                    __stcg(&g_gates[t & 1][r1g], a1 + e1);
                }
            }
            if (doex) {
                if (ex_gate) {
                    float e2 = b_ih[ex_r] + b_hh[ex_r]
                             + W_ih[ex_r * 3 + 0] * x0
                             + W_ih[ex_r * 3 + 1] * x1
                             + W_ih[ex_r * 3 + 2] * x2;
                    __stcg(&g_gates[t & 1][ex_r], a2 + e2);
                } else {
                    __stcg(&g_dall[t - 1][ex_r], a2 + Wd_b[ex_r]);
                }
            }
        }

        gridbar();

        if (t < T_) {
            const float* gp = g_gates[t & 1];
            // j0 = tid
            {
                float gi = __ldcg(gp + tid);
                float gf = __ldcg(gp + D_ + tid);
                float gg = __ldcg(gp + 2 * D_ + tid);
                float go = __ldcg(gp + 3 * D_ + tid);
                float i_ = fast_sigmoid(gi);
                float f_ = fast_sigmoid(gf);
                float g_ = fast_tanh(gg);
                float o_ = fast_sigmoid(go);
                c0 = fmaf(f_, c0, i_ * g_);
                float h = o_ * fast_tanh(c0);
                hsm[tid] = h;
                if (b == 0) out_hs[(size_t)t * D_ + tid] = h;
            }
            // j1 = tid + NT
            {
                int j = tid + NT;
                float gi = __ldcg(gp + j);
                float gf = __ldcg(gp + D_ + j);
                float gg = __ldcg(gp + 2 * D_ + j);
                float go = __ldcg(gp + 3 * D_ + j);
                float i_ = fast_sigmoid(gi);
                float f_ = fast_sigmoid(gf);
                float g_ = fast_tanh(gg);
                float o_ = fast_sigmoid(go);
                c1 = fmaf(f_, c1, i_ * g_);
                float h = o_ * fast_tanh(c1);
                hsm[j] = h;
                if (b == 0) out_hs[(size_t)t * D_ + j] = h;
            }
            __syncthreads();
        }
    }

    // =======================================================================
    // Stage 2: logits[t][l] = sum_v tanh(enc[l][v] + d_t[v]) * v_w[v] + v_b
    // (smem: d at offset 0, vw at 8KB — weights no longer needed)
    // =======================================================================
    float* sd  = (float*)dynsm;
    float* svw = (float*)(dynsm + D_ * 4);
    for (int j = tid; j < V_; j += NT) svw[j] = v_w[j];
    const float vb = v_b[0];

    for (int item = b; item < T_ * 9; item += NBLK) {
        const int t  = item / 9;
        const int ch = item % 9;
        __syncthreads();
        for (int j = tid; j < V_; j += NT) sd[j] = __ldcg(&g_dall[t][j]);
        __syncthreads();

        const int lbase = ch * 57;
        const float4* d4 = (const float4*)sd;
        const float4* w4 = (const float4*)svw;
        for (int l = lbase + wid; l < lbase + 57; l += NW) {
            const float4* e4 = (const float4*)(g_enc + (size_t)l * V_);
            float acc = 0.f;
            #pragma unroll 2
            for (int k = lane; k < V_ / 4; k += 32) {
                float4 e = __ldcg(e4 + k);
                float4 d = d4[k];
                float4 w = w4[k];
                acc = fmaf(fast_tanh(e.x + d.x), w.x, acc);
                acc = fmaf(fast_tanh(e.y + d.y), w.y, acc);
                acc = fmaf(fast_tanh(e.z + d.z), w.z, acc);
                acc = fmaf(fast_tanh(e.w + d.w), w.w, acc);
            }
            #pragma unroll
            for (int off = 16; off > 0; off >>= 1)
                acc += __shfl_down_sync(0xffffffffu, acc, off);
            if (lane == 0) __stcg(&out_logits[(size_t)t * LP1 + l], acc + vb);
        }
    }

    gridbar();

    // =======================================================================
    // Stage 3: losses
    // =======================================================================
    if (b < T_) {
        const int t = b;
        const float* lg = out_logits + (size_t)t * LP1;

        float m = -1e30f;
        for (int i = tid; i < LP1; i += NT) m = fmaxf(m, __ldcg(lg + i));
        #pragma unroll
        for (int off = 16; off > 0; off >>= 1)
            m = fmaxf(m, __shfl_down_sync(0xffffffffu, m, off));
        if (lane == 0) red[wid] = m;
        __syncthreads();
        if (wid == 0) {
            float mm = (lane < NW) ? red[lane] : -1e30f;
            #pragma unroll
            for (int off = 16; off > 0; off >>= 1)
                mm = fmaxf(mm, __shfl_down_sync(0xffffffffu, mm, off));
            if (lane == 0) red[0] = mm;
        }
        __syncthreads();
        m = red[0];
        __syncthreads();

        float s = 0.f;
        for (int i = tid; i < LP1; i += NT) s += expf(__ldcg(lg + i) - m);
        #pragma unroll
        for (int off = 16; off > 0; off >>= 1)
            s += __shfl_down_sync(0xffffffffu, s, off);
        if (lane == 0) red[wid] = s;
        __syncthreads();
        if (wid == 0) {
            float ss = (lane < NW) ? red[lane] : 0.f;
            #pragma unroll
            for (int off = 16; off > 0; off >>= 1)
                ss += __shfl_down_sync(0xffffffffu, ss, off);
            if (lane == 0) {
                int tgt = (t < 64) ? positions[t] : LSEQ;
                out_losses[t] = m + logf(ss) - __ldcg(lg + tgt);
            }
        }
    }
}

// ---------------------------------------------------------------------------
extern "C" void kernel_launch(void* const* d_in, const int* in_sizes, int n_in,
                              void* d_out, int out_size) {
    const float* initial_state = (const float*)d_in[0];
    const float* enc_states    = (const float*)d_in[1];
    const float* seq_points    = (const float*)d_in[2];
    const int*   positions     = (const int*)  d_in[3];
    const float* W_ih          = (const float*)d_in[4];
    const float* W_hh          = (const float*)d_in[5];
    const float* b_ih          = (const float*)d_in[6];
    const float* b_hh          = (const float*)d_in[7];
    const float* We_w          = (const float*)d_in[8];
    const float* We_b          = (const float*)d_in[9];
    const float* Wd_w          = (const float*)d_in[10];
    const float* Wd_b          = (const float*)d_in[11];
    const float* v_w           = (const float*)d_in[12];
    const float* v_b           = (const float*)d_in[13];

    float* out        = (float*)d_out;
    float* out_logits = out;
    float* out_hs     = out + T_ * LP1;
    float* out_losses = out + T_ * LP1 + T_ * D_;

    static int smem_set = 0;
    if (!smem_set) {
        cudaFuncSetAttribute(decoder_kernel,
                             cudaFuncAttributeMaxDynamicSharedMemorySize, SMEM_BYTES);
        smem_set = 1;
    }

    decoder_kernel<<<NBLK, NT, SMEM_BYTES>>>(
        initial_state, enc_states, seq_points, positions,
        W_ih, W_hh, b_ih, b_hh, We_w, We_b, Wd_w, Wd_b,
        v_w, v_b, out_logits, out_hs, out_losses);
}

// round 6
// speedup vs baseline: 1.0514x; 1.0514x over previous
#include <cuda_runtime.h>
#include <cuda_fp16.h>
#include <math.h>

// ---------------------------------------------------------------------------
#define D_    2048
#define V_    2048
#define LSEQ  512
#define LP1   513
#define T_    65
#define G4    8192

#define NBLK  148
#define NT    1024
#define NW    32

#define SROWS 54              // SMEM-resident gate rows per block (148*54 = 7992)
#define LEFT  200             // leftover gate rows 7992..8191 (L2 fp16)
#define XROWS (LEFT + V_)     // g_w16 rows: leftover gates + all Wd rows

// dynamic smem layout (bytes)
#define OFF_H     (SROWS * D_ * 2)          // 221184: h[2048] floats
#define OFF_RED   (OFF_H + D_ * 4)          // 229376: red[32]
#define SMEM_BYTES (OFF_RED + 128)          // 229504

// ---------------------------------------------------------------------------
__device__ __half g_w16[(size_t)XROWS * D_];   // fp16: 200 leftover gate rows + Wd
__device__ float g_enc[LP1 * V_];              // enc_proj
__device__ float g_gates[2][G4];               // double-buffered gates
__device__ float g_hall[T_ * D_];              // h_t for all steps (aligned copy)
__device__ float g_dp[4][T_ * V_];             // K-split partial d
__device__ volatile unsigned g_arr[256];       // barrier arrival slots
__device__ volatile unsigned g_rel;            // barrier release flag (persistent epoch)

// ---------------------------------------------------------------------------
// Flag barrier: no atomics. Each block release-stores its slot; block 0
// polls all slots then release-stores g_rel; others poll g_rel.
// gen is monotonic across launches via epoch base read from g_rel at entry.
// ---------------------------------------------------------------------------
__device__ __forceinline__ void gridbar(unsigned gen) {
    __syncthreads();
    const int tid = threadIdx.x;
    if (tid == 0)
        asm volatile("st.release.gpu.global.u32 [%0], %1;"
                     :: "l"((void*)&g_arr[blockIdx.x]), "r"(gen) : "memory");
    if (blockIdx.x == 0) {
        if (tid < NBLK) {
            unsigned v;
            do {
                asm volatile("ld.acquire.gpu.global.u32 %0, [%1];"
                             : "=r"(v) : "l"((const void*)&g_arr[tid]) : "memory");
            } while ((int)(v - gen) < 0);
        }
        __syncthreads();
        if (tid == 0)
            asm volatile("st.release.gpu.global.u32 [%0], %1;"
                         :: "l"((void*)&g_rel), "r"(gen) : "memory");
    } else {
        if (tid == 0) {
            unsigned v;
            do {
                asm volatile("ld.acquire.gpu.global.u32 %0, [%1];"
                             : "=r"(v) : "l"((const void*)&g_rel) : "memory");
            } while ((int)(v - gen) < 0);
        }
        __syncthreads();
    }
}

// ---------------------------------------------------------------------------
// Branchless rational tanh (Eigen 13/6) + Newton reciprocal (no MUFU).
// Used in the recurrence (error must not compound).
// ---------------------------------------------------------------------------
__device__ __forceinline__ float fast_tanh(float x) {
    float xc = fminf(fmaxf(x, -7.90531110763549805f), 7.90531110763549805f);
    float x2 = xc * xc;
    float p = -2.76076847742355e-16f;
    p = fmaf(p, x2, 2.00018790482477e-13f);
    p = fmaf(p, x2, -8.60467152213735e-11f);
    p = fmaf(p, x2, 5.12229709037114e-08f);
    p = fmaf(p, x2, 1.48572235717979e-05f);
    p = fmaf(p, x2, 6.37261928875436e-04f);
    p = fmaf(p, x2, 4.89352455891786e-03f);
    p *= xc;
    float q = 1.19825839466702e-06f;
    q = fmaf(q, x2, 1.18534705686654e-04f);
    q = fmaf(q, x2, 2.26843463243900e-03f);
    q = fmaf(q, x2, 4.89352518554385e-03f);
    float r = __uint_as_float(0x7EF311C3u - __float_as_uint(q));
    r = r * fmaf(-q, r, 2.0f);
    r = r * fmaf(-q, r, 2.0f);
    r = r * fmaf(-q, r, 2.0f);
    r = r * fmaf(-q, r, 2.0f);
    return p * r;
}
__device__ __forceinline__ float fast_sigmoid(float x) {
    return fmaf(0.5f, fast_tanh(0.5f * x), 0.5f);
}
// HW tanh (stage 2 only; errors don't compound there)
__device__ __forceinline__ float hw_tanh(float x) {
    float y;
    asm("tanh.approx.f32 %0, %1;" : "=f"(y) : "f"(x));
    return y;
}

// fp16 dot8
__device__ __forceinline__ float dot8(uint4 u, float4 ha, float4 hb, float acc) {
    float2 f0 = __half22float2(*(__half2*)&u.x);
    float2 f1 = __half22float2(*(__half2*)&u.y);
    float2 f2 = __half22float2(*(__half2*)&u.z);
    float2 f3 = __half22float2(*(__half2*)&u.w);
    acc = fmaf(f0.x, ha.x, acc);
    acc = fmaf(f0.y, ha.y, acc);
    acc = fmaf(f1.x, ha.z, acc);
    acc = fmaf(f1.y, ha.w, acc);
    acc = fmaf(f2.x, hb.x, acc);
    acc = fmaf(f2.y, hb.y, acc);
    acc = fmaf(f3.x, hb.z, acc);
    acc = fmaf(f3.y, hb.w, acc);
    return acc;
}

// mma.sync m16n8k16 row.col f32.f16.f16.f32
__device__ __forceinline__ void mma16816(float* c, const unsigned* a, const unsigned* b) {
    asm volatile(
        "mma.sync.aligned.m16n8k16.row.col.f32.f16.f16.f32 "
        "{%0,%1,%2,%3}, {%4,%5,%6,%7}, {%8,%9}, {%0,%1,%2,%3};"
        : "+f"(c[0]), "+f"(c[1]), "+f"(c[2]), "+f"(c[3])
        : "r"(a[0]), "r"(a[1]), "r"(a[2]), "r"(a[3]), "r"(b[0]), "r"(b[1]));
}

#define KS 40

__global__ void __launch_bounds__(NT, 1)
decoder_kernel(const float* __restrict__ initial_state,
               const float* __restrict__ enc_states,
               const float* __restrict__ seq_points,
               const int*   __restrict__ positions,
               const float* __restrict__ W_ih,
               const float* __restrict__ W_hh,
               const float* __restrict__ b_ih,
               const float* __restrict__ b_hh,
               const float* __restrict__ We_w,
               const float* __restrict__ We_b,
               const float* __restrict__ Wd_w,
               const float* __restrict__ Wd_b,
               const float* __restrict__ v_w,
               const float* __restrict__ v_b,
               float* __restrict__ out_logits,
               float* __restrict__ out_hs,
               float* __restrict__ out_losses)
{
    extern __shared__ __align__(16) char dynsm[];
    __half* wsm = (__half*)dynsm;
    float*  hsm = (float*)(dynsm + OFF_H);
    float*  red = (float*)(dynsm + OFF_RED);

    const int tid  = threadIdx.x;
    const int wid  = tid >> 5;
    const int lane = tid & 31;
    const int b    = blockIdx.x;

    const unsigned base = g_rel;     // epoch base (stable until first barrier)
    unsigned gen = base;

    // =======================================================================
    // Phase G: enc_proj GEMM on tensor cores (blocks 0..79)
    // =======================================================================
    if (b < 80) {
        __half* ga = (__half*)dynsm;
        __half* gb = ga + 128 * KS;
        const int l0 = (b / 16) * 128;
        const int v0 = (b % 16) * 128;
        const int warpM = wid >> 3;
        const int warpN = wid & 7;
        const int g  = lane >> 2;
        const int t2 = (lane & 3) * 2;
        const int ldrow = tid >> 3;
        const int ldk   = (tid & 7) * 4;

        float c[2][2][4];
        #pragma unroll
        for (int m = 0; m < 2; ++m)
            #pragma unroll
            for (int n = 0; n < 2; ++n)
                #pragma unroll
                for (int q = 0; q < 4; ++q) c[m][n][q] = 0.f;

        for (int k0 = 0; k0 < D_; k0 += 32) {
            int gl = l0 + ldrow; if (gl > 512) gl = 512;
            float4 av = *(const float4*)&enc_states[(size_t)gl * D_ + k0 + ldk];
            float4 bv = *(const float4*)&We_w[(size_t)(v0 + ldrow) * D_ + k0 + ldk];
            __syncthreads();
            *(__half2*)&ga[ldrow * KS + ldk]     = __floats2half2_rn(av.x, av.y);
            *(__half2*)&ga[ldrow * KS + ldk + 2] = __floats2half2_rn(av.z, av.w);
            *(__half2*)&gb[ldrow * KS + ldk]     = __floats2half2_rn(bv.x, bv.y);
            *(__half2*)&gb[ldrow * KS + ldk + 2] = __floats2half2_rn(bv.z, bv.w);
            __syncthreads();

            #pragma unroll
            for (int ks = 0; ks < 2; ++ks) {
                const int kb = ks * 16;
                unsigned a[2][4], bb[2][2];
                #pragma unroll
                for (int m = 0; m < 2; ++m) {
                    int ar = warpM * 32 + m * 16;
                    a[m][0] = *(const unsigned*)&ga[(ar + g) * KS + kb + t2];
                    a[m][1] = *(const unsigned*)&ga[(ar + g + 8) * KS + kb + t2];
                    a[m][2] = *(const unsigned*)&ga[(ar + g) * KS + kb + t2 + 8];
                    a[m][3] = *(const unsigned*)&ga[(ar + g + 8) * KS + kb + t2 + 8];
                }
                #pragma unroll
                for (int n = 0; n < 2; ++n) {
                    int br = warpN * 16 + n * 8;
                    bb[n][0] = *(const unsigned*)&gb[(br + g) * KS + kb + t2];
                    bb[n][1] = *(const unsigned*)&gb[(br + g) * KS + kb + t2 + 8];
                }
                #pragma unroll
                for (int m = 0; m < 2; ++m)
                    #pragma unroll
                    for (int n = 0; n < 2; ++n)
                        mma16816(c[m][n], a[m], bb[n]);
            }
        }

        #pragma unroll
        for (int m = 0; m < 2; ++m) {
            #pragma unroll
            for (int n = 0; n < 2; ++n) {
                int lrow = l0 + warpM * 32 + m * 16 + g;
                int vcol = v0 + warpN * 16 + n * 8 + t2;
                if (lrow < LP1) {
                    g_enc[(size_t)lrow * V_ + vcol]     = c[m][n][0] + We_b[vcol];
                    g_enc[(size_t)lrow * V_ + vcol + 1] = c[m][n][1] + We_b[vcol + 1];
                }
                if (lrow + 8 < LP1) {
                    g_enc[(size_t)(lrow + 8) * V_ + vcol]     = c[m][n][2] + We_b[vcol];
                    g_enc[(size_t)(lrow + 8) * V_ + vcol + 1] = c[m][n][3] + We_b[vcol + 1];
                }
            }
        }
        __syncthreads();
    }

    // =======================================================================
    // Prologue A (all blocks): 54 gate rows -> SMEM fp16
    // =======================================================================
    {
        const float4* src = (const float4*)(W_hh + (size_t)b * SROWS * D_);
        uint2* dst = (uint2*)wsm;
        const int n4 = SROWS * D_ / 4;
        for (int i = tid; i < n4; i += NT) {
            float4 v = src[i];
            __half2 h01 = __floats2half2_rn(v.x, v.y);
            __half2 h23 = __floats2half2_rn(v.z, v.w);
            uint2 pk; pk.x = *(unsigned*)&h01; pk.y = *(unsigned*)&h23;
            dst[i] = pk;
        }
    }
    // Prologue B (blocks 80..147 only): leftover gates + Wd -> g_w16 fp16
    if (b >= 80) {
        const int NG4 = LEFT * (D_ / 4);
        const int NT4 = XROWS * (D_ / 4);
        const float4* lg = (const float4*)(W_hh + (size_t)(G4 - LEFT) * D_);
        uint2* dst = (uint2*)g_w16;
        for (int i = (b - 80) * NT + tid; i < NT4; i += (NBLK - 80) * NT) {
            float4 v = (i < NG4) ? lg[i] : ((const float4*)Wd_w)[i - NG4];
            __half2 h01 = __floats2half2_rn(v.x, v.y);
            __half2 h23 = __floats2half2_rn(v.z, v.w);
            uint2 pk; pk.x = *(unsigned*)&h01; pk.y = *(unsigned*)&h23;
            dst[i] = pk;
        }
    }

    // init recurrence state
    float c0 = 0.f, c1 = 0.f;
    hsm[tid]      = initial_state[tid];
    hsm[tid + NT] = initial_state[tid + NT];
    gridbar(++gen);

    // =======================================================================
    // Stage 1: 65 LSTM steps, one barrier each.
    //   warps 0..7: 6-7 SMEM weight rows each; warps 8..17 (b<20): 1 L2 row.
    // =======================================================================
    {
        int nrows = 0, sbase = 0;
        if (wid < 6)      { nrows = 7; sbase = wid * 7; }
        else if (wid < 8) { nrows = 6; sbase = 42 + (wid - 6) * 6; }
        const bool seven = (wid < 6);
        const bool hasex = (wid >= 8) && (wid < 18) && (b < 20);
        const int  exi   = b * 10 + (wid - 8);          // g_w16 row, 0..199
        const int  rexg  = NBLK * SROWS + exi;          // global gate row
        const uint4* wr4 = (const uint4*)wsm + sbase * (D_ / 8);
        const uint4* exw = (const uint4*)(g_w16 + (size_t)(hasex ? exi : 0) * D_);

        for (int t = 0; t < T_; ++t) {
            const float4* h4 = (const float4*)hsm;
            float acc[7] = {0.f, 0.f, 0.f, 0.f, 0.f, 0.f, 0.f};
            float aex = 0.f;

            if (nrows) {
                #pragma unroll 2
                for (int k8 = lane; k8 < 256; k8 += 32) {
                    float4 ha = h4[2 * k8];
                    float4 hb = h4[2 * k8 + 1];
                    #pragma unroll
                    for (int rr = 0; rr < 6; ++rr)
                        acc[rr] = dot8(wr4[rr * 256 + k8], ha, hb, acc[rr]);
                    if (seven)
                        acc[6] = dot8(wr4[6 * 256 + k8], ha, hb, acc[6]);
                }
            }
            if (hasex) {
                #pragma unroll 2
                for (int k8 = lane; k8 < 256; k8 += 32) {
                    float4 ha = h4[2 * k8];
                    float4 hb = h4[2 * k8 + 1];
                    aex = dot8(__ldcg(exw + k8), ha, hb, aex);
                }
            }
            #pragma unroll
            for (int off = 16; off > 0; off >>= 1) {
                #pragma unroll
                for (int rr = 0; rr < 7; ++rr)
                    acc[rr] += __shfl_down_sync(0xffffffffu, acc[rr], off);
                aex += __shfl_down_sync(0xffffffffu, aex, off);
            }

            if (lane == 0) {
                float x0 = 0.f, x1 = 0.f, x2 = 1.f;
                if (t >= 1) {
                    int pos = positions[t - 1];
                    x0 = seq_points[pos * 3 + 0];
                    x1 = seq_points[pos * 3 + 1];
                    x2 = seq_points[pos * 3 + 2];
                }
                if (nrows) {
                    #pragma unroll
                    for (int rr = 0; rr < 7; ++rr) {
                        if (rr < nrows) {
                            int r = b * SROWS + sbase + rr;
                            float e = b_ih[r] + b_hh[r]
                                    + W_ih[r * 3 + 0] * x0
                                    + W_ih[r * 3 + 1] * x1
                                    + W_ih[r * 3 + 2] * x2;
                            __stcg(&g_gates[t & 1][r], acc[rr] + e);
                        }
                    }
                }
                if (hasex) {
                    float e = b_ih[rexg] + b_hh[rexg]
                            + W_ih[rexg * 3 + 0] * x0
                            + W_ih[rexg * 3 + 1] * x1
                            + W_ih[rexg * 3 + 2] * x2;
                    __stcg(&g_gates[t & 1][rexg], aex + e);
                }
            }

            gridbar(++gen);

            // redundant per-block LSTM update (2 elements per thread)
            {
                const float* gp = g_gates[t & 1];
                const bool wrb = (b == t);          // writer block for step t
                {
                    float gi = __ldcg(gp + tid);
                    float gf = __ldcg(gp + D_ + tid);
                    float gg = __ldcg(gp + 2 * D_ + tid);
                    float go = __ldcg(gp + 3 * D_ + tid);
                    float i_ = fast_sigmoid(gi);
                    float f_ = fast_sigmoid(gf);
                    float g_ = fast_tanh(gg);
                    float o_ = fast_sigmoid(go);
                    c0 = fmaf(f_, c0, i_ * g_);
                    float h = o_ * fast_tanh(c0);
                    hsm[tid] = h;
                    if (wrb) {
                        out_hs[(size_t)t * D_ + tid] = h;
                        g_hall[(size_t)t * D_ + tid] = h;
                    }
                }
                {
                    int j = tid + NT;
                    float gi = __ldcg(gp + j);
                    float gf = __ldcg(gp + D_ + j);
                    float gg = __ldcg(gp + 2 * D_ + j);
                    float go = __ldcg(gp + 3 * D_ + j);
                    float i_ = fast_sigmoid(gi);
                    float f_ = fast_sigmoid(gf);
                    float g_ = fast_tanh(gg);
                    float o_ = fast_sigmoid(go);
                    c1 = fmaf(f_, c1, i_ * g_);
                    float h = o_ * fast_tanh(c1);
                    hsm[j] = h;
                    if (wrb) {
                        out_hs[(size_t)t * D_ + j] = h;
                        g_hall[(size_t)t * D_ + j] = h;
                    }
                }
                __syncthreads();
            }
        }
    }

    gridbar(++gen);     // all h published

    // =======================================================================
    // D-pass: d[t][v] = Wd[v,:] . h_t  as TC GEMM, K-split 4 partials.
    // blocks 0..63: tile (128 t-pad) x (128 v), K range 512.
    // =======================================================================
    if (b < 64) {
        __half* sa = (__half*)dynsm;
        __half* sb = sa + 128 * KS;
        const int v0 = (b & 15) * 128;
        const int ksp = b >> 4;                 // 0..3
        const int klo = ksp * 512;
        const int warpM = wid >> 3;
        const int warpN = wid & 7;
        const int g  = lane >> 2;
        const int t2 = (lane & 3) * 2;
        const int ldrow = tid >> 3;
        const int ldk   = (tid & 7) * 4;

        float c[2][2][4];
        #pragma unroll
        for (int m = 0; m < 2; ++m)
            #pragma unroll
            for (int n = 0; n < 2; ++n)
                #pragma unroll
                for (int q = 0; q < 4; ++q) c[m][n][q] = 0.f;

        for (int k0 = klo; k0 < klo + 512; k0 += 32) {
            int tt = ldrow; if (tt > 64) tt = 64;
            float4 av = __ldcg((const float4*)&g_hall[(size_t)tt * D_ + k0 + ldk]);
            uint2  bv = __ldcg((const uint2*)&g_w16[(size_t)(LEFT + v0 + ldrow) * D_ + k0 + ldk]);
            __syncthreads();
            *(__half2*)&sa[ldrow * KS + ldk]     = __floats2half2_rn(av.x, av.y);
            *(__half2*)&sa[ldrow * KS + ldk + 2] = __floats2half2_rn(av.z, av.w);
            *(uint2*)&sb[ldrow * KS + ldk] = bv;
            __syncthreads();

            #pragma unroll
            for (int ks = 0; ks < 2; ++ks) {
                const int kb = ks * 16;
                unsigned a[2][4], bb[2][2];
                #pragma unroll
                for (int m = 0; m < 2; ++m) {
                    int ar = warpM * 32 + m * 16;
                    a[m][0] = *(const unsigned*)&sa[(ar + g) * KS + kb + t2];
                    a[m][1] = *(const unsigned*)&sa[(ar + g + 8) * KS + kb + t2];
                    a[m][2] = *(const unsigned*)&sa[(ar + g) * KS + kb + t2 + 8];
                    a[m][3] = *(const unsigned*)&sa[(ar + g + 8) * KS + kb + t2 + 8];
                }
                #pragma unroll
                for (int n = 0; n < 2; ++n) {
                    int br = warpN * 16 + n * 8;
                    bb[n][0] = *(const unsigned*)&sb[(br + g) * KS + kb + t2];
                    bb[n][1] = *(const unsigned*)&sb[(br + g) * KS + kb + t2 + 8];
                }
                #pragma unroll
                for (int m = 0; m < 2; ++m)
                    #pragma unroll
                    for (int n = 0; n < 2; ++n)
                        mma16816(c[m][n], a[m], bb[n]);
            }
        }

        float* dp = g_dp[ksp];
        #pragma unroll
        for (int m = 0; m < 2; ++m) {
            #pragma unroll
            for (int n = 0; n < 2; ++n) {
                int trow = warpM * 32 + m * 16 + g;
                int vcol = v0 + warpN * 16 + n * 8 + t2;
                if (trow < T_) {
                    dp[(size_t)trow * V_ + vcol]     = c[m][n][0];
                    dp[(size_t)trow * V_ + vcol + 1] = c[m][n][1];
                }
                if (trow + 8 < T_) {
                    dp[(size_t)(trow + 8) * V_ + vcol]     = c[m][n][2];
                    dp[(size_t)(trow + 8) * V_ + vcol + 1] = c[m][n][3];
                }
            }
        }
    }

    gridbar(++gen);

    // =======================================================================
    // Stage 2: logits[t][l] = sum_v tanh(enc[l][v] + d_t[v]) * v_w[v] + v_b
    // (MUFU tanh; d summed from 4 partials + bias)
    // =======================================================================
    float* sd  = (float*)dynsm;
    float* svw = (float*)(dynsm + D_ * 4);
    for (int j = tid; j < V_; j += NT) svw[j] = v_w[j];
    const float vb = v_b[0];

    for (int item = b; item < T_ * 9; item += NBLK) {
        const int t  = item / 9;
        const int ch = item % 9;
        __syncthreads();
        for (int j = tid; j < V_; j += NT) {
            float d = __ldcg(&g_dp[0][(size_t)t * V_ + j])
                    + __ldcg(&g_dp[1][(size_t)t * V_ + j])
                    + __ldcg(&g_dp[2][(size_t)t * V_ + j])
                    + __ldcg(&g_dp[3][(size_t)t * V_ + j])
                    + Wd_b[j];
            sd[j] = d;
        }
        __syncthreads();

        const int lbase = ch * 57;
        const float4* d4 = (const float4*)sd;
        const float4* w4 = (const float4*)svw;
        for (int l = lbase + wid; l < lbase + 57; l += NW) {
            const float4* e4 = (const float4*)(g_enc + (size_t)l * V_);
            float acc = 0.f;
            #pragma unroll 2
            for (int k = lane; k < V_ / 4; k += 32) {
                float4 e = __ldcg(e4 + k);
                float4 d = d4[k];
                float4 w = w4[k];
                acc = fmaf(hw_tanh(e.x + d.x), w.x, acc);
                acc = fmaf(hw_tanh(e.y + d.y), w.y, acc);
                acc = fmaf(hw_tanh(e.z + d.z), w.z, acc);
                acc = fmaf(hw_tanh(e.w + d.w), w.w, acc);
            }
            #pragma unroll
            for (int off = 16; off > 0; off >>= 1)
                acc += __shfl_down_sync(0xffffffffu, acc, off);
            if (lane == 0) __stcg(&out_logits[(size_t)t * LP1 + l], acc + vb);
        }
    }

    gridbar(++gen);

    // =======================================================================
    // Stage 3: losses
    // =======================================================================
    if (b < T_) {
        const int t = b;
        const float* lg = out_logits + (size_t)t * LP1;

        float m = -1e30f;
        for (int i = tid; i < LP1; i += NT) m = fmaxf(m, __ldcg(lg + i));
        #pragma unroll
        for (int off = 16; off > 0; off >>= 1)
            m = fmaxf(m, __shfl_down_sync(0xffffffffu, m, off));
        if (lane == 0) red[wid] = m;
        __syncthreads();
        if (wid == 0) {
            float mm = (lane < NW) ? red[lane] : -1e30f;
            #pragma unroll
            for (int off = 16; off > 0; off >>= 1)
                mm = fmaxf(mm, __shfl_down_sync(0xffffffffu, mm, off));
            if (lane == 0) red[0] = mm;
        }
        __syncthreads();
        m = red[0];
        __syncthreads();

        float s = 0.f;
        for (int i = tid; i < LP1; i += NT) s += expf(__ldcg(lg + i) - m);
        #pragma unroll
        for (int off = 16; off > 0; off >>= 1)
            s += __shfl_down_sync(0xffffffffu, s, off);
        if (lane == 0) red[wid] = s;
        __syncthreads();
        if (wid == 0) {
            float ss = (lane < NW) ? red[lane] : 0.f;
            #pragma unroll
            for (int off = 16; off > 0; off >>= 1)
                ss += __shfl_down_sync(0xffffffffu, ss, off);
            if (lane == 0) {
                int tgt = (t < 64) ? positions[t] : LSEQ;
                out_losses[t] = m + logf(ss) - __ldcg(lg + tgt);
            }
        }
    }
}

// ---------------------------------------------------------------------------
extern "C" void kernel_launch(void* const* d_in, const int* in_sizes, int n_in,
                              void* d_out, int out_size) {
    const float* initial_state = (const float*)d_in[0];
    const float* enc_states    = (const float*)d_in[1];
    const float* seq_points    = (const float*)d_in[2];
    const int*   positions     = (const int*)  d_in[3];
    const float* W_ih          = (const float*)d_in[4];
    const float* W_hh          = (const float*)d_in[5];
    const float* b_ih          = (const float*)d_in[6];
    const float* b_hh          = (const float*)d_in[7];
    const float* We_w          = (const float*)d_in[8];
    const float* We_b          = (const float*)d_in[9];
    const float* Wd_w          = (const float*)d_in[10];
    const float* Wd_b          = (const float*)d_in[11];
    const float* v_w           = (const float*)d_in[12];
    const float* v_b           = (const float*)d_in[13];

    float* out        = (float*)d_out;
    float* out_logits = out;
    float* out_hs     = out + T_ * LP1;
    float* out_losses = out + T_ * LP1 + T_ * D_;

    static int smem_set = 0;
    if (!smem_set) {
        cudaFuncSetAttribute(decoder_kernel,
                             cudaFuncAttributeMaxDynamicSharedMemorySize, SMEM_BYTES);
        smem_set = 1;
    }

    decoder_kernel<<<NBLK, NT, SMEM_BYTES>>>(
        initial_state, enc_states, seq_points, positions,
        W_ih, W_hh, b_ih, b_hh, We_w, We_b, Wd_w, Wd_b,
        v_w, v_b, out_logits, out_hs, out_losses);
}

// round 7
// speedup vs baseline: 1.0834x; 1.0304x over previous
#include <cuda_runtime.h>
#include <cuda_fp16.h>
#include <math.h>

// ---------------------------------------------------------------------------
#define D_    2048
#define V_    2048
#define LSEQ  512
#define LP1   513
#define T_    65
#define G4    8192

#define NBLK  148
#define NT    1024
#define NW    32

#define SROWS 54              // SMEM-resident gate rows per block (148*54 = 7992)
#define LEFT  200             // leftover gate rows 7992..8191 (L2 fp16)
#define XROWS (LEFT + V_)     // g_w16 rows: leftover gates + all Wd rows

#define CANARY 0x7FC0DEADu   // NaN payload: cannot be produced by gate math

// dynamic smem layout (bytes)
#define OFF_H     (SROWS * D_ * 2)          // 221184: h[2048] floats
#define OFF_RED   (OFF_H + D_ * 4)          // 229376: red[32]
#define SMEM_BYTES (OFF_RED + 128)          // 229504

// ---------------------------------------------------------------------------
__device__ __half g_w16[(size_t)XROWS * D_];   // fp16: 200 leftover gate rows + Wd
__device__ float g_enc[LP1 * V_];              // enc_proj
__device__ float g_gates[T_][G4];              // per-step gate buffers, interleaved [elem][ifgo]
__device__ float g_hall[T_ * D_];              // h_t for all steps
__device__ float g_dp[4][T_ * V_];             // K-split partial d
__device__ volatile unsigned g_arr[256];       // barrier arrival slots
__device__ volatile unsigned g_rel;            // barrier release flag (persistent epoch)

// ---------------------------------------------------------------------------
// Structural grid barrier (used only 4x per launch)
// ---------------------------------------------------------------------------
__device__ __forceinline__ void gridbar(unsigned gen) {
    __syncthreads();
    const int tid = threadIdx.x;
    if (tid == 0)
        asm volatile("st.release.gpu.global.u32 [%0], %1;"
                     :: "l"((void*)&g_arr[blockIdx.x]), "r"(gen) : "memory");
    if (blockIdx.x == 0) {
        if (tid < NBLK) {
            unsigned v;
            do {
                asm volatile("ld.acquire.gpu.global.u32 %0, [%1];"
                             : "=r"(v) : "l"((const void*)&g_arr[tid]) : "memory");
            } while ((int)(v - gen) < 0);
        }
        __syncthreads();
        if (tid == 0)
            asm volatile("st.release.gpu.global.u32 [%0], %1;"
                         :: "l"((void*)&g_rel), "r"(gen) : "memory");
    } else {
        if (tid == 0) {
            unsigned v;
            do {
                asm volatile("ld.acquire.gpu.global.u32 %0, [%1];"
                             : "=r"(v) : "l"((const void*)&g_rel) : "memory");
            } while ((int)(v - gen) < 0);
        }
        __syncthreads();
    }
}

// ---------------------------------------------------------------------------
// Data-flow primitives: gates carry their own readiness (canary sentinel)
// ---------------------------------------------------------------------------
__device__ __forceinline__ void store_gate(float* p, float v) {
    asm volatile("st.global.cg.f32 [%0], %1;" :: "l"(p), "f"(v) : "memory");
}
__device__ __forceinline__ float4 poll_gates4(const float* p) {
    unsigned x, y, z, w;
    asm volatile("ld.global.cg.v4.u32 {%0,%1,%2,%3}, [%4];"
                 : "=r"(x), "=r"(y), "=r"(z), "=r"(w) : "l"(p) : "memory");
    while (x == CANARY || y == CANARY || z == CANARY || w == CANARY) {
        __nanosleep(64);
        asm volatile("ld.global.cg.v4.u32 {%0,%1,%2,%3}, [%4];"
                     : "=r"(x), "=r"(y), "=r"(z), "=r"(w) : "l"(p) : "memory");
    }
    float4 r;
    r.x = __uint_as_float(x); r.y = __uint_as_float(y);
    r.z = __uint_as_float(z); r.w = __uint_as_float(w);
    return r;
}

// ---------------------------------------------------------------------------
// Branchless rational tanh (Eigen 13/6) + Newton reciprocal (no MUFU).
// ---------------------------------------------------------------------------
__device__ __forceinline__ float fast_tanh(float x) {
    float xc = fminf(fmaxf(x, -7.90531110763549805f), 7.90531110763549805f);
    float x2 = xc * xc;
    float p = -2.76076847742355e-16f;
    p = fmaf(p, x2, 2.00018790482477e-13f);
    p = fmaf(p, x2, -8.60467152213735e-11f);
    p = fmaf(p, x2, 5.12229709037114e-08f);
    p = fmaf(p, x2, 1.48572235717979e-05f);
    p = fmaf(p, x2, 6.37261928875436e-04f);
    p = fmaf(p, x2, 4.89352455891786e-03f);
    p *= xc;
    float q = 1.19825839466702e-06f;
    q = fmaf(q, x2, 1.18534705686654e-04f);
    q = fmaf(q, x2, 2.26843463243900e-03f);
    q = fmaf(q, x2, 4.89352518554385e-03f);
    float r = __uint_as_float(0x7EF311C3u - __float_as_uint(q));
    r = r * fmaf(-q, r, 2.0f);
    r = r * fmaf(-q, r, 2.0f);
    r = r * fmaf(-q, r, 2.0f);
    return p * r;
}
__device__ __forceinline__ float fast_sigmoid(float x) {
    return fmaf(0.5f, fast_tanh(0.5f * x), 0.5f);
}
__device__ __forceinline__ float hw_tanh(float x) {
    float y;
    asm("tanh.approx.f32 %0, %1;" : "=f"(y) : "f"(x));
    return y;
}

// fp16 dot8
__device__ __forceinline__ float dot8(uint4 u, float4 ha, float4 hb, float acc) {
    float2 f0 = __half22float2(*(__half2*)&u.x);
    float2 f1 = __half22float2(*(__half2*)&u.y);
    float2 f2 = __half22float2(*(__half2*)&u.z);
    float2 f3 = __half22float2(*(__half2*)&u.w);
    acc = fmaf(f0.x, ha.x, acc);
    acc = fmaf(f0.y, ha.y, acc);
    acc = fmaf(f1.x, ha.z, acc);
    acc = fmaf(f1.y, ha.w, acc);
    acc = fmaf(f2.x, hb.x, acc);
    acc = fmaf(f2.y, hb.y, acc);
    acc = fmaf(f3.x, hb.z, acc);
    acc = fmaf(f3.y, hb.w, acc);
    return acc;
}

// mma.sync m16n8k16 row.col f32.f16.f16.f32
__device__ __forceinline__ void mma16816(float* c, const unsigned* a, const unsigned* b) {
    asm volatile(
        "mma.sync.aligned.m16n8k16.row.col.f32.f16.f16.f32 "
        "{%0,%1,%2,%3}, {%4,%5,%6,%7}, {%8,%9}, {%0,%1,%2,%3};"
        : "+f"(c[0]), "+f"(c[1]), "+f"(c[2]), "+f"(c[3])
        : "r"(a[0]), "r"(a[1]), "r"(a[2]), "r"(a[3]), "r"(b[0]), "r"(b[1]));
}

#define KS 40

__global__ void __launch_bounds__(NT, 1)
decoder_kernel(const float* __restrict__ initial_state,
               const float* __restrict__ enc_states,
               const float* __restrict__ seq_points,
               const int*   __restrict__ positions,
               const float* __restrict__ W_ih,
               const float* __restrict__ W_hh,
               const float* __restrict__ b_ih,
               const float* __restrict__ b_hh,
               const float* __restrict__ We_w,
               const float* __restrict__ We_b,
               const float* __restrict__ Wd_w,
               const float* __restrict__ Wd_b,
               const float* __restrict__ v_w,
               const float* __restrict__ v_b,
               float* __restrict__ out_logits,
               float* __restrict__ out_hs,
               float* __restrict__ out_losses)
{
    extern __shared__ __align__(16) char dynsm[];
    __half* wsm = (__half*)dynsm;
    float*  hsm = (float*)(dynsm + OFF_H);
    float*  red = (float*)(dynsm + OFF_RED);

    const int tid  = threadIdx.x;
    const int wid  = tid >> 5;
    const int lane = tid & 31;
    const int b    = blockIdx.x;

    const unsigned base = g_rel;
    unsigned gen = base;

    // =======================================================================
    // Phase G: enc_proj GEMM on tensor cores (blocks 0..79)
    // =======================================================================
    if (b < 80) {
        __half* ga = (__half*)dynsm;
        __half* gb = ga + 128 * KS;
        const int l0 = (b / 16) * 128;
        const int v0 = (b % 16) * 128;
        const int warpM = wid >> 3;
        const int warpN = wid & 7;
        const int g  = lane >> 2;
        const int t2 = (lane & 3) * 2;
        const int ldrow = tid >> 3;
        const int ldk   = (tid & 7) * 4;

        float c[2][2][4];
        #pragma unroll
        for (int m = 0; m < 2; ++m)
            #pragma unroll
            for (int n = 0; n < 2; ++n)
                #pragma unroll
                for (int q = 0; q < 4; ++q) c[m][n][q] = 0.f;

        for (int k0 = 0; k0 < D_; k0 += 32) {
            int gl = l0 + ldrow; if (gl > 512) gl = 512;
            float4 av = *(const float4*)&enc_states[(size_t)gl * D_ + k0 + ldk];
            float4 bv = *(const float4*)&We_w[(size_t)(v0 + ldrow) * D_ + k0 + ldk];
            __syncthreads();
            *(__half2*)&ga[ldrow * KS + ldk]     = __floats2half2_rn(av.x, av.y);
            *(__half2*)&ga[ldrow * KS + ldk + 2] = __floats2half2_rn(av.z, av.w);
            *(__half2*)&gb[ldrow * KS + ldk]     = __floats2half2_rn(bv.x, bv.y);
            *(__half2*)&gb[ldrow * KS + ldk + 2] = __floats2half2_rn(bv.z, bv.w);
            __syncthreads();

            #pragma unroll
            for (int ks = 0; ks < 2; ++ks) {
                const int kb = ks * 16;
                unsigned a[2][4], bb[2][2];
                #pragma unroll
                for (int m = 0; m < 2; ++m) {
                    int ar = warpM * 32 + m * 16;
                    a[m][0] = *(const unsigned*)&ga[(ar + g) * KS + kb + t2];
                    a[m][1] = *(const unsigned*)&ga[(ar + g + 8) * KS + kb + t2];
                    a[m][2] = *(const unsigned*)&ga[(ar + g) * KS + kb + t2 + 8];
                    a[m][3] = *(const unsigned*)&ga[(ar + g + 8) * KS + kb + t2 + 8];
                }
                #pragma unroll
                for (int n = 0; n < 2; ++n) {
                    int br = warpN * 16 + n * 8;
                    bb[n][0] = *(const unsigned*)&gb[(br + g) * KS + kb + t2];
                    bb[n][1] = *(const unsigned*)&gb[(br + g) * KS + kb + t2 + 8];
                }
                #pragma unroll
                for (int m = 0; m < 2; ++m)
                    #pragma unroll
                    for (int n = 0; n < 2; ++n)
                        mma16816(c[m][n], a[m], bb[n]);
            }
        }

        #pragma unroll
        for (int m = 0; m < 2; ++m) {
            #pragma unroll
            for (int n = 0; n < 2; ++n) {
                int lrow = l0 + warpM * 32 + m * 16 + g;
                int vcol = v0 + warpN * 16 + n * 8 + t2;
                if (lrow < LP1) {
                    g_enc[(size_t)lrow * V_ + vcol]     = c[m][n][0] + We_b[vcol];
                    g_enc[(size_t)lrow * V_ + vcol + 1] = c[m][n][1] + We_b[vcol + 1];
                }
                if (lrow + 8 < LP1) {
                    g_enc[(size_t)(lrow + 8) * V_ + vcol]     = c[m][n][2] + We_b[vcol];
                    g_enc[(size_t)(lrow + 8) * V_ + vcol + 1] = c[m][n][3] + We_b[vcol + 1];
                }
            }
        }
        __syncthreads();
    }

    // =======================================================================
    // Prologue A (all blocks): 54 gate rows -> SMEM fp16
    // =======================================================================
    {
        const float4* src = (const float4*)(W_hh + (size_t)b * SROWS * D_);
        uint2* dst = (uint2*)wsm;
        const int n4 = SROWS * D_ / 4;
        for (int i = tid; i < n4; i += NT) {
            float4 v = src[i];
            __half2 h01 = __floats2half2_rn(v.x, v.y);
            __half2 h23 = __floats2half2_rn(v.z, v.w);
            uint2 pk; pk.x = *(unsigned*)&h01; pk.y = *(unsigned*)&h23;
            dst[i] = pk;
        }
    }
    // Prologue B (blocks 80..147): leftover gates + Wd -> g_w16 fp16
    if (b >= 80) {
        const int NG4 = LEFT * (D_ / 4);
        const int NT4 = XROWS * (D_ / 4);
        const float4* lg = (const float4*)(W_hh + (size_t)(G4 - LEFT) * D_);
        uint2* dst = (uint2*)g_w16;
        for (int i = (b - 80) * NT + tid; i < NT4; i += (NBLK - 80) * NT) {
            float4 v = (i < NG4) ? lg[i] : ((const float4*)Wd_w)[i - NG4];
            __half2 h01 = __floats2half2_rn(v.x, v.y);
            __half2 h23 = __floats2half2_rn(v.z, v.w);
            uint2 pk; pk.x = *(unsigned*)&h01; pk.y = *(unsigned*)&h23;
            dst[i] = pk;
        }
    }
    // Prologue C (blocks 0..79): poison all per-step gate buffers
    if (b < 80) {
        unsigned* gg = (unsigned*)g_gates;
        const int n = T_ * G4;
        for (int i = b * NT + tid; i < n; i += 80 * NT)
            gg[i] = CANARY;
    }

    // init recurrence state
    float c0 = 0.f, c1 = 0.f;
    hsm[tid]      = initial_state[tid];
    hsm[tid + NT] = initial_state[tid + NT];
    gridbar(++gen);

    // =======================================================================
    // Stage 1: 65 LSTM steps. NO grid barrier: per-step gate buffers are
    // poisoned, producers store, consumers poll their own values.
    //   warps 0..5: 7 SMEM rows; warps 6..7: 6 SMEM rows;
    //   warp 8: 1 L2 row (all blocks); warp 9: 1 L2 row (b<52).
    // =======================================================================
    {
        int nrows = 0, sbase = 0;
        if (wid < 6)      { nrows = 7; sbase = wid * 7; }
        else if (wid < 8) { nrows = 6; sbase = 42 + (wid - 6) * 6; }
        const bool seven = (wid < 6);
        const bool hasex = (wid == 8) || (wid == 9 && b < 52);
        const int  exi   = (wid == 8) ? b : (148 + b);   // 0..199
        const int  rex   = NBLK * SROWS + exi;           // global gate row
        const uint4* wr4 = (const uint4*)wsm + sbase * (D_ / 8);
        const uint4* exw = (const uint4*)(g_w16 + (size_t)(hasex ? exi : 0) * D_);

        for (int t = 0; t < T_; ++t) {
            float* gbuf = g_gates[t];
            // ---- produce ----
            if (nrows | (int)hasex) {
                const float4* h4 = (const float4*)hsm;
                float acc[7] = {0.f, 0.f, 0.f, 0.f, 0.f, 0.f, 0.f};
                float aex = 0.f;
                if (nrows) {
                    #pragma unroll 2
                    for (int k8 = lane; k8 < 256; k8 += 32) {
                        float4 ha = h4[2 * k8];
                        float4 hb = h4[2 * k8 + 1];
                        #pragma unroll
                        for (int rr = 0; rr < 6; ++rr)
                            acc[rr] = dot8(wr4[rr * 256 + k8], ha, hb, acc[rr]);
                        if (seven)
                            acc[6] = dot8(wr4[6 * 256 + k8], ha, hb, acc[6]);
                    }
                } else {
                    #pragma unroll 2
                    for (int k8 = lane; k8 < 256; k8 += 32) {
                        float4 ha = h4[2 * k8];
                        float4 hb = h4[2 * k8 + 1];
                        aex = dot8(__ldcg(exw + k8), ha, hb, aex);
                    }
                }
                #pragma unroll
                for (int off = 16; off > 0; off >>= 1) {
                    #pragma unroll
                    for (int rr = 0; rr < 7; ++rr)
                        acc[rr] += __shfl_down_sync(0xffffffffu, acc[rr], off);
                    aex += __shfl_down_sync(0xffffffffu, aex, off);
                }
                if (lane == 0) {
                    float x0 = 0.f, x1 = 0.f, x2 = 1.f;
                    if (t >= 1) {
                        int pos = positions[t - 1];
                        x0 = seq_points[pos * 3 + 0];
                        x1 = seq_points[pos * 3 + 1];
                        x2 = seq_points[pos * 3 + 2];
                    }
                    if (nrows) {
                        #pragma unroll
                        for (int rr = 0; rr < 7; ++rr) {
                            if (rr < nrows) {
                                int r = b * SROWS + sbase + rr;
                                float e = b_ih[r] + b_hh[r]
                                        + W_ih[r * 3 + 0] * x0
                                        + W_ih[r * 3 + 1] * x1
                                        + W_ih[r * 3 + 2] * x2;
                                store_gate(&gbuf[((r & 2047) << 2) | (r >> 11)], acc[rr] + e);
                            }
                        }
                    } else {
                        float e = b_ih[rex] + b_hh[rex]
                                + W_ih[rex * 3 + 0] * x0
                                + W_ih[rex * 3 + 1] * x1
                                + W_ih[rex * 3 + 2] * x2;
                        store_gate(&gbuf[((rex & 2047) << 2) | (rex >> 11)], aex + e);
                    }
                }
            }
            __syncthreads();     // all hsm reads done before update overwrites

            // ---- consume: poll own gates (data-flow sync across blocks) ----
            float4 q0 = poll_gates4(gbuf + (tid << 2));
            float4 q1 = poll_gates4(gbuf + ((tid + NT) << 2));

            // ---- update ----
            {
                float i_ = fast_sigmoid(q0.x);
                float f_ = fast_sigmoid(q0.y);
                float g_ = fast_tanh(q0.z);
                float o_ = fast_sigmoid(q0.w);
                c0 = fmaf(f_, c0, i_ * g_);
                float h = o_ * fast_tanh(c0);
                hsm[tid] = h;
                if (b == t) {
                    out_hs[(size_t)t * D_ + tid] = h;
                    g_hall[(size_t)t * D_ + tid] = h;
                }
            }
            {
                float i_ = fast_sigmoid(q1.x);
                float f_ = fast_sigmoid(q1.y);
                float g_ = fast_tanh(q1.z);
                float o_ = fast_sigmoid(q1.w);
                c1 = fmaf(f_, c1, i_ * g_);
                float h = o_ * fast_tanh(c1);
                hsm[tid + NT] = h;
                if (b == t) {
                    out_hs[(size_t)t * D_ + tid + NT] = h;
                    g_hall[(size_t)t * D_ + tid + NT] = h;
                }
            }
            __syncthreads();     // hsm complete before next matvec
        }
    }

    gridbar(++gen);     // all h published

    // =======================================================================
    // D-pass: d[t][v] = Wd[v,:] . h_t  as TC GEMM, K-split 4 partials.
    // =======================================================================
    if (b < 64) {
        __half* sa = (__half*)dynsm;
        __half* sb = sa + 128 * KS;
        const int v0 = (b & 15) * 128;
        const int ksp = b >> 4;
        const int klo = ksp * 512;
        const int warpM = wid >> 3;
        const int warpN = wid & 7;
        const int g  = lane >> 2;
        const int t2 = (lane & 3) * 2;
        const int ldrow = tid >> 3;
        const int ldk   = (tid & 7) * 4;

        float c[2][2][4];
        #pragma unroll
        for (int m = 0; m < 2; ++m)
            #pragma unroll
            for (int n = 0; n < 2; ++n)
                #pragma unroll
                for (int q = 0; q < 4; ++q) c[m][n][q] = 0.f;

        for (int k0 = klo; k0 < klo + 512; k0 += 32) {
            int tt = ldrow; if (tt > 64) tt = 64;
            float4 av = __ldcg((const float4*)&g_hall[(size_t)tt * D_ + k0 + ldk]);
            uint2  bv = __ldcg((const uint2*)&g_w16[(size_t)(LEFT + v0 + ldrow) * D_ + k0 + ldk]);
            __syncthreads();
            *(__half2*)&sa[ldrow * KS + ldk]     = __floats2half2_rn(av.x, av.y);
            *(__half2*)&sa[ldrow * KS + ldk + 2] = __floats2half2_rn(av.z, av.w);
            *(uint2*)&sb[ldrow * KS + ldk] = bv;
            __syncthreads();

            #pragma unroll
            for (int ks = 0; ks < 2; ++ks) {
                const int kb = ks * 16;
                unsigned a[2][4], bb[2][2];
                #pragma unroll
                for (int m = 0; m < 2; ++m) {
                    int ar = warpM * 32 + m * 16;
                    a[m][0] = *(const unsigned*)&sa[(ar + g) * KS + kb + t2];
                    a[m][1] = *(const unsigned*)&sa[(ar + g + 8) * KS + kb + t2];
                    a[m][2] = *(const unsigned*)&sa[(ar + g) * KS + kb + t2 + 8];
                    a[m][3] = *(const unsigned*)&sa[(ar + g + 8) * KS + kb + t2 + 8];
                }
                #pragma unroll
                for (int n = 0; n < 2; ++n) {
                    int br = warpN * 16 + n * 8;
                    bb[n][0] = *(const unsigned*)&sb[(br + g) * KS + kb + t2];
                    bb[n][1] = *(const unsigned*)&sb[(br + g) * KS + kb + t2 + 8];
                }
                #pragma unroll
                for (int m = 0; m < 2; ++m)
                    #pragma unroll
                    for (int n = 0; n < 2; ++n)
                        mma16816(c[m][n], a[m], bb[n]);
            }
        }

        float* dp = g_dp[ksp];
        #pragma unroll
        for (int m = 0; m < 2; ++m) {
            #pragma unroll
            for (int n = 0; n < 2; ++n) {
                int trow = warpM * 32 + m * 16 + g;
                int vcol = v0 + warpN * 16 + n * 8 + t2;
                if (trow < T_) {
                    dp[(size_t)trow * V_ + vcol]     = c[m][n][0];
                    dp[(size_t)trow * V_ + vcol + 1] = c[m][n][1];
                }
                if (trow + 8 < T_) {
                    dp[(size_t)(trow + 8) * V_ + vcol]     = c[m][n][2];
                    dp[(size_t)(trow + 8) * V_ + vcol + 1] = c[m][n][3];
                }
            }
        }
    }

    gridbar(++gen);

    // =======================================================================
    // Stage 2: logits[t][l] = sum_v tanh(enc[l][v] + d_t[v]) * v_w[v] + v_b
    // =======================================================================
    float* sd  = (float*)dynsm;
    float* svw = (float*)(dynsm + D_ * 4);
    for (int j = tid; j < V_; j += NT) svw[j] = v_w[j];
    const float vb = v_b[0];

    for (int item = b; item < T_ * 9; item += NBLK) {
        const int t  = item / 9;
        const int ch = item % 9;
        __syncthreads();
        for (int j = tid; j < V_; j += NT) {
            float d = __ldcg(&g_dp[0][(size_t)t * V_ + j])
                    + __ldcg(&g_dp[1][(size_t)t * V_ + j])
                    + __ldcg(&g_dp[2][(size_t)t * V_ + j])
                    + __ldcg(&g_dp[3][(size_t)t * V_ + j])
                    + Wd_b[j];
            sd[j] = d;
        }
        __syncthreads();

        const int lbase = ch * 57;
        const float4* d4 = (const float4*)sd;
        const float4* w4 = (const float4*)svw;
        for (int l = lbase + wid; l < lbase + 57; l += NW) {
            const float4* e4 = (const float4*)(g_enc + (size_t)l * V_);
            float acc = 0.f;
            #pragma unroll 2
            for (int k = lane; k < V_ / 4; k += 32) {
                float4 e = __ldcg(e4 + k);
                float4 d = d4[k];
                float4 w = w4[k];
                acc = fmaf(hw_tanh(e.x + d.x), w.x, acc);
                acc = fmaf(hw_tanh(e.y + d.y), w.y, acc);
                acc = fmaf(hw_tanh(e.z + d.z), w.z, acc);
                acc = fmaf(hw_tanh(e.w + d.w), w.w, acc);
            }
            #pragma unroll
            for (int off = 16; off > 0; off >>= 1)
                acc += __shfl_down_sync(0xffffffffu, acc, off);
            if (lane == 0) __stcg(&out_logits[(size_t)t * LP1 + l], acc + vb);
        }
    }

    gridbar(++gen);

    // =======================================================================
    // Stage 3: losses
    // =======================================================================
    if (b < T_) {
        const int t = b;
        const float* lg = out_logits + (size_t)t * LP1;

        float m = -1e30f;
        for (int i = tid; i < LP1; i += NT) m = fmaxf(m, __ldcg(lg + i));
        #pragma unroll
        for (int off = 16; off > 0; off >>= 1)
            m = fmaxf(m, __shfl_down_sync(0xffffffffu, m, off));
        if (lane == 0) red[wid] = m;
        __syncthreads();
        if (wid == 0) {
            float mm = (lane < NW) ? red[lane] : -1e30f;
            #pragma unroll
            for (int off = 16; off > 0; off >>= 1)
                mm = fmaxf(mm, __shfl_down_sync(0xffffffffu, mm, off));
            if (lane == 0) red[0] = mm;
        }
        __syncthreads();
        m = red[0];
        __syncthreads();

        float s = 0.f;
        for (int i = tid; i < LP1; i += NT) s += expf(__ldcg(lg + i) - m);
        #pragma unroll
        for (int off = 16; off > 0; off >>= 1)
            s += __shfl_down_sync(0xffffffffu, s, off);
        if (lane == 0) red[wid] = s;
        __syncthreads();
        if (wid == 0) {
            float ss = (lane < NW) ? red[lane] : 0.f;
            #pragma unroll
            for (int off = 16; off > 0; off >>= 1)
                ss += __shfl_down_sync(0xffffffffu, ss, off);
            if (lane == 0) {
                int tgt = (t < 64) ? positions[t] : LSEQ;
                out_losses[t] = m + logf(ss) - __ldcg(lg + tgt);
            }
        }
    }
}

// ---------------------------------------------------------------------------
extern "C" void kernel_launch(void* const* d_in, const int* in_sizes, int n_in,
                              void* d_out, int out_size) {
    const float* initial_state = (const float*)d_in[0];
    const float* enc_states    = (const float*)d_in[1];
    const float* seq_points    = (const float*)d_in[2];
    const int*   positions     = (const int*)  d_in[3];
    const float* W_ih          = (const float*)d_in[4];
    const float* W_hh          = (const float*)d_in[5];
    const float* b_ih          = (const float*)d_in[6];
    const float* b_hh          = (const float*)d_in[7];
    const float* We_w          = (const float*)d_in[8];
    const float* We_b          = (const float*)d_in[9];
    const float* Wd_w          = (const float*)d_in[10];
    const float* Wd_b          = (const float*)d_in[11];
    const float* v_w           = (const float*)d_in[12];
    const float* v_b           = (const float*)d_in[13];

    float* out        = (float*)d_out;
    float* out_logits = out;
    float* out_hs     = out + T_ * LP1;
    float* out_losses = out + T_ * LP1 + T_ * D_;

    static int smem_set = 0;
    if (!smem_set) {
        cudaFuncSetAttribute(decoder_kernel,
                             cudaFuncAttributeMaxDynamicSharedMemorySize, SMEM_BYTES);
        smem_set = 1;
    }

    decoder_kernel<<<NBLK, NT, SMEM_BYTES>>>(
        initial_state, enc_states, seq_points, positions,
        W_ih, W_hh, b_ih, b_hh, We_w, We_b, Wd_w, Wd_b,
        v_w, v_b, out_logits, out_hs, out_losses);
}

// round 8
// speedup vs baseline: 1.1370x; 1.0495x over previous
#include <cuda_runtime.h>
#include <cuda_fp16.h>
#include <math.h>

// ---------------------------------------------------------------------------
#define D_    2048
#define V_    2048
#define LSEQ  512
#define LP1   513
#define T_    65
#define G4    8192

#define NBLK  148
#define NT    1024
#define NW    32

#define SROWS 54              // SMEM-resident gate rows per block (148*54 = 7992)
#define LEFT  200             // leftover gate rows 7992..8191 (L2 fp16)
#define XROWS (LEFT + V_)     // g_w16 rows: leftover gates + all Wd rows

// dynamic smem layout (bytes)
#define OFF_H     (SROWS * D_ * 2)          // 221184: h[2048] floats
#define OFF_RED   (OFF_H + D_ * 4)          // 229376: red[32]
#define OFF_FLG   (OFF_RED + 128)           // 229504: 4 chunk flags
#define SMEM_BYTES (OFF_FLG + 16)           // 229520

// ---------------------------------------------------------------------------
__device__ __half g_w16[(size_t)XROWS * D_];   // fp16: 200 leftover gate rows + Wd
__device__ float g_enc[LP1 * V_];              // enc_proj
__device__ float g_gates[T_][G4];              // per-step gates, interleaved [elem][ifgo]
__device__ float g_hall[T_ * D_];              // h_t for all steps
__device__ float g_dp[4][T_ * V_];             // K-split partial d
__device__ unsigned g_gflag[NBLK * 32];        // per-block step flags (128B padded)
__device__ volatile unsigned g_arr[256];       // structural barrier slots
__device__ volatile unsigned g_rel;            // structural barrier release flag

// ---------------------------------------------------------------------------
__device__ __forceinline__ unsigned ld_acq(const unsigned* p) {
    unsigned v;
    asm volatile("ld.acquire.gpu.global.u32 %0, [%1];" : "=r"(v) : "l"(p) : "memory");
    return v;
}
__device__ __forceinline__ void st_rel(unsigned* p, unsigned v) {
    asm volatile("st.release.gpu.global.u32 [%0], %1;" :: "l"(p), "r"(v) : "memory");
}

// Structural grid barrier (4x per launch)
__device__ __forceinline__ void gridbar(unsigned gen) {
    __syncthreads();
    const int tid = threadIdx.x;
    if (tid == 0)
        asm volatile("st.release.gpu.global.u32 [%0], %1;"
                     :: "l"((void*)&g_arr[blockIdx.x]), "r"(gen) : "memory");
    if (blockIdx.x == 0) {
        if (tid < NBLK) {
            unsigned v;
            do {
                asm volatile("ld.acquire.gpu.global.u32 %0, [%1];"
                             : "=r"(v) : "l"((const void*)&g_arr[tid]) : "memory");
            } while ((int)(v - gen) < 0);
        }
        __syncthreads();
        if (tid == 0)
            asm volatile("st.release.gpu.global.u32 [%0], %1;"
                         :: "l"((void*)&g_rel), "r"(gen) : "memory");
    } else {
        if (tid == 0) {
            unsigned v;
            do {
                asm volatile("ld.acquire.gpu.global.u32 %0, [%1];"
                             : "=r"(v) : "l"((const void*)&g_rel) : "memory");
            } while ((int)(v - gen) < 0);
        }
        __syncthreads();
    }
}

// ---------------------------------------------------------------------------
// Branchless rational tanh (Eigen 13/6) + Newton reciprocal (no MUFU).
// ---------------------------------------------------------------------------
__device__ __forceinline__ float fast_tanh(float x) {
    float xc = fminf(fmaxf(x, -7.90531110763549805f), 7.90531110763549805f);
    float x2 = xc * xc;
    float p = -2.76076847742355e-16f;
    p = fmaf(p, x2, 2.00018790482477e-13f);
    p = fmaf(p, x2, -8.60467152213735e-11f);
    p = fmaf(p, x2, 5.12229709037114e-08f);
    p = fmaf(p, x2, 1.48572235717979e-05f);
    p = fmaf(p, x2, 6.37261928875436e-04f);
    p = fmaf(p, x2, 4.89352455891786e-03f);
    p *= xc;
    float q = 1.19825839466702e-06f;
    q = fmaf(q, x2, 1.18534705686654e-04f);
    q = fmaf(q, x2, 2.26843463243900e-03f);
    q = fmaf(q, x2, 4.89352518554385e-03f);
    float r = __uint_as_float(0x7EF311C3u - __float_as_uint(q));
    r = r * fmaf(-q, r, 2.0f);
    r = r * fmaf(-q, r, 2.0f);
    r = r * fmaf(-q, r, 2.0f);
    return p * r;
}
__device__ __forceinline__ float fast_sigmoid(float x) {
    return fmaf(0.5f, fast_tanh(0.5f * x), 0.5f);
}
__device__ __forceinline__ float hw_tanh(float x) {
    float y;
    asm("tanh.approx.f32 %0, %1;" : "=f"(y) : "f"(x));
    return y;
}

// fp16 dot8
__device__ __forceinline__ float dot8(uint4 u, float4 ha, float4 hb, float acc) {
    float2 f0 = __half22float2(*(__half2*)&u.x);
    float2 f1 = __half22float2(*(__half2*)&u.y);
    float2 f2 = __half22float2(*(__half2*)&u.z);
    float2 f3 = __half22float2(*(__half2*)&u.w);
    acc = fmaf(f0.x, ha.x, acc);
    acc = fmaf(f0.y, ha.y, acc);
    acc = fmaf(f1.x, ha.z, acc);
    acc = fmaf(f1.y, ha.w, acc);
    acc = fmaf(f2.x, hb.x, acc);
    acc = fmaf(f2.y, hb.y, acc);
    acc = fmaf(f3.x, hb.z, acc);
    acc = fmaf(f3.y, hb.w, acc);
    return acc;
}

// mma.sync m16n8k16 row.col f32.f16.f16.f32
__device__ __forceinline__ void mma16816(float* c, const unsigned* a, const unsigned* b) {
    asm volatile(
        "mma.sync.aligned.m16n8k16.row.col.f32.f16.f16.f32 "
        "{%0,%1,%2,%3}, {%4,%5,%6,%7}, {%8,%9}, {%0,%1,%2,%3};"
        : "+f"(c[0]), "+f"(c[1]), "+f"(c[2]), "+f"(c[3])
        : "r"(a[0]), "r"(a[1]), "r"(a[2]), "r"(a[3]), "r"(b[0]), "r"(b[1]));
}

__device__ __forceinline__ float4 ldcg4(const float* p) {
    float4 v;
    asm volatile("ld.global.cg.v4.f32 {%0,%1,%2,%3}, [%4];"
                 : "=f"(v.x), "=f"(v.y), "=f"(v.z), "=f"(v.w) : "l"(p) : "memory");
    return v;
}

#define KS 40

__global__ void __launch_bounds__(NT, 1)
decoder_kernel(const float* __restrict__ initial_state,
               const float* __restrict__ enc_states,
               const float* __restrict__ seq_points,
               const int*   __restrict__ positions,
               const float* __restrict__ W_ih,
               const float* __restrict__ W_hh,
               const float* __restrict__ b_ih,
               const float* __restrict__ b_hh,
               const float* __restrict__ We_w,
               const float* __restrict__ We_b,
               const float* __restrict__ Wd_w,
               const float* __restrict__ Wd_b,
               const float* __restrict__ v_w,
               const float* __restrict__ v_b,
               float* __restrict__ out_logits,
               float* __restrict__ out_hs,
               float* __restrict__ out_losses)
{
    extern __shared__ __align__(16) char dynsm[];
    __half* wsm = (__half*)dynsm;
    float*  hsm = (float*)(dynsm + OFF_H);
    float*  red = (float*)(dynsm + OFF_RED);
    volatile int* sflg = (volatile int*)(dynsm + OFF_FLG);

    const int tid  = threadIdx.x;
    const int wid  = tid >> 5;
    const int lane = tid & 31;
    const int b    = blockIdx.x;

    const unsigned gbase = g_rel;                 // structural-barrier epoch base
    const unsigned fb    = g_gflag[b * 32];       // step-flag epoch base (uniform)
    unsigned gen = gbase;

    // =======================================================================
    // Phase G: enc_proj GEMM on tensor cores (blocks 0..79)
    // =======================================================================
    if (b < 80) {
        __half* ga = (__half*)dynsm;
        __half* gb = ga + 128 * KS;
        const int l0 = (b / 16) * 128;
        const int v0 = (b % 16) * 128;
        const int warpM = wid >> 3;
        const int warpN = wid & 7;
        const int g  = lane >> 2;
        const int t2 = (lane & 3) * 2;
        const int ldrow = tid >> 3;
        const int ldk   = (tid & 7) * 4;

        float c[2][2][4];
        #pragma unroll
        for (int m = 0; m < 2; ++m)
            #pragma unroll
            for (int n = 0; n < 2; ++n)
                #pragma unroll
                for (int q = 0; q < 4; ++q) c[m][n][q] = 0.f;

        for (int k0 = 0; k0 < D_; k0 += 32) {
            int gl = l0 + ldrow; if (gl > 512) gl = 512;
            float4 av = *(const float4*)&enc_states[(size_t)gl * D_ + k0 + ldk];
            float4 bv = *(const float4*)&We_w[(size_t)(v0 + ldrow) * D_ + k0 + ldk];
            __syncthreads();
            *(__half2*)&ga[ldrow * KS + ldk]     = __floats2half2_rn(av.x, av.y);
            *(__half2*)&ga[ldrow * KS + ldk + 2] = __floats2half2_rn(av.z, av.w);
            *(__half2*)&gb[ldrow * KS + ldk]     = __floats2half2_rn(bv.x, bv.y);
            *(__half2*)&gb[ldrow * KS + ldk + 2] = __floats2half2_rn(bv.z, bv.w);
            __syncthreads();

            #pragma unroll
            for (int ks = 0; ks < 2; ++ks) {
                const int kb = ks * 16;
                unsigned a[2][4], bb[2][2];
                #pragma unroll
                for (int m = 0; m < 2; ++m) {
                    int ar = warpM * 32 + m * 16;
                    a[m][0] = *(const unsigned*)&ga[(ar + g) * KS + kb + t2];
                    a[m][1] = *(const unsigned*)&ga[(ar + g + 8) * KS + kb + t2];
                    a[m][2] = *(const unsigned*)&ga[(ar + g) * KS + kb + t2 + 8];
                    a[m][3] = *(const unsigned*)&ga[(ar + g + 8) * KS + kb + t2 + 8];
                }
                #pragma unroll
                for (int n = 0; n < 2; ++n) {
                    int br = warpN * 16 + n * 8;
                    bb[n][0] = *(const unsigned*)&gb[(br + g) * KS + kb + t2];
                    bb[n][1] = *(const unsigned*)&gb[(br + g) * KS + kb + t2 + 8];
                }
                #pragma unroll
                for (int m = 0; m < 2; ++m)
                    #pragma unroll
                    for (int n = 0; n < 2; ++n)
                        mma16816(c[m][n], a[m], bb[n]);
            }
        }

        #pragma unroll
        for (int m = 0; m < 2; ++m) {
            #pragma unroll
            for (int n = 0; n < 2; ++n) {
                int lrow = l0 + warpM * 32 + m * 16 + g;
                int vcol = v0 + warpN * 16 + n * 8 + t2;
                if (lrow < LP1) {
                    g_enc[(size_t)lrow * V_ + vcol]     = c[m][n][0] + We_b[vcol];
                    g_enc[(size_t)lrow * V_ + vcol + 1] = c[m][n][1] + We_b[vcol + 1];
                }
                if (lrow + 8 < LP1) {
                    g_enc[(size_t)(lrow + 8) * V_ + vcol]     = c[m][n][2] + We_b[vcol];
                    g_enc[(size_t)(lrow + 8) * V_ + vcol + 1] = c[m][n][3] + We_b[vcol + 1];
                }
            }
        }
        __syncthreads();
    }

    // =======================================================================
    // Prologue A (all blocks): 54 gate rows -> SMEM fp16
    // =======================================================================
    {
        const float4* src = (const float4*)(W_hh + (size_t)b * SROWS * D_);
        uint2* dst = (uint2*)wsm;
        const int n4 = SROWS * D_ / 4;
        for (int i = tid; i < n4; i += NT) {
            float4 v = src[i];
            __half2 h01 = __floats2half2_rn(v.x, v.y);
            __half2 h23 = __floats2half2_rn(v.z, v.w);
            uint2 pk; pk.x = *(unsigned*)&h01; pk.y = *(unsigned*)&h23;
            dst[i] = pk;
        }
    }
    // Prologue B (blocks 80..147): leftover gates + Wd -> g_w16 fp16
    if (b >= 80) {
        const int NG4 = LEFT * (D_ / 4);
        const int NT4 = XROWS * (D_ / 4);
        const float4* lg = (const float4*)(W_hh + (size_t)(G4 - LEFT) * D_);
        uint2* dst = (uint2*)g_w16;
        for (int i = (b - 80) * NT + tid; i < NT4; i += (NBLK - 80) * NT) {
            float4 v = (i < NG4) ? lg[i] : ((const float4*)Wd_w)[i - NG4];
            __half2 h01 = __floats2half2_rn(v.x, v.y);
            __half2 h23 = __floats2half2_rn(v.z, v.w);
            uint2 pk; pk.x = *(unsigned*)&h01; pk.y = *(unsigned*)&h23;
            dst[i] = pk;
        }
    }

    // init recurrence state + chunk flags
    hsm[tid]      = initial_state[tid];
    hsm[tid + NT] = initial_state[tid + NT];
    if (tid < 4) sflg[tid] = 0;
    gridbar(++gen);

    // =======================================================================
    // Stage 1: 65 steps. Warp-specialized intra-block pipeline.
    //   warps 0..9  : producers (matvec, chunk-paced by smem flags)
    //   warps 10..25: updaters (poll global flags, LSTM update in 4 chunks)
    //   warps 26..31: idle
    // =======================================================================
    if (wid < 10) {
        // ---- producers ----
        int nrows = 0, sbase = 0;
        if (wid < 6)      { nrows = 7; sbase = wid * 7; }
        else if (wid < 8) { nrows = 6; sbase = 42 + (wid - 6) * 6; }
        const bool seven = (wid < 6);
        const bool hasex = (wid == 8) || (wid == 9 && b < 52);
        const int  exi   = (wid == 8) ? b : (148 + b);
        const int  rex   = NBLK * SROWS + exi;
        const uint4* wr4 = (const uint4*)wsm + sbase * (D_ / 8);
        const uint4* exw = (const uint4*)(g_w16 + (size_t)(hasex ? exi : 0) * D_);

        for (int t = 0; t < T_; ++t) {
            float* gbuf = g_gates[t];
            float acc[7] = {0.f, 0.f, 0.f, 0.f, 0.f, 0.f, 0.f};
            float aex = 0.f;
            const float4* h4 = (const float4*)hsm;

            if (nrows | (int)hasex) {
                #pragma unroll
                for (int cp = 0; cp < 4; ++cp) {
                    while (sflg[cp] < t) { }           // wait h_{t-1} chunk
                    asm volatile("" ::: "memory");
                    #pragma unroll
                    for (int i = 2 * cp; i < 2 * cp + 2; ++i) {
                        int k8 = lane + (i << 5);
                        float4 ha = h4[2 * k8];
                        float4 hb = h4[2 * k8 + 1];
                        if (nrows) {
                            #pragma unroll
                            for (int rr = 0; rr < 6; ++rr)
                                acc[rr] = dot8(wr4[rr * 256 + k8], ha, hb, acc[rr]);
                            if (seven)
                                acc[6] = dot8(wr4[6 * 256 + k8], ha, hb, acc[6]);
                        } else {
                            aex = dot8(__ldcg(exw + k8), ha, hb, aex);
                        }
                    }
                }
                #pragma unroll
                for (int off = 16; off > 0; off >>= 1) {
                    #pragma unroll
                    for (int rr = 0; rr < 7; ++rr)
                        acc[rr] += __shfl_down_sync(0xffffffffu, acc[rr], off);
                    aex += __shfl_down_sync(0xffffffffu, aex, off);
                }
                if (lane == 0) {
                    float x0 = 0.f, x1 = 0.f, x2 = 1.f;
                    if (t >= 1) {
                        int pos = positions[t - 1];
                        x0 = seq_points[pos * 3 + 0];
                        x1 = seq_points[pos * 3 + 1];
                        x2 = seq_points[pos * 3 + 2];
                    }
                    if (nrows) {
                        #pragma unroll
                        for (int rr = 0; rr < 7; ++rr) {
                            if (rr < nrows) {
                                int r = b * SROWS + sbase + rr;
                                float e = b_ih[r] + b_hh[r]
                                        + W_ih[r * 3 + 0] * x0
                                        + W_ih[r * 3 + 1] * x1
                                        + W_ih[r * 3 + 2] * x2;
                                asm volatile("st.global.cg.f32 [%0], %1;"
                                    :: "l"(&gbuf[((r & 2047) << 2) | (r >> 11)]), "f"(acc[rr] + e) : "memory");
                            }
                        }
                    } else {
                        float e = b_ih[rex] + b_hh[rex]
                                + W_ih[rex * 3 + 0] * x0
                                + W_ih[rex * 3 + 1] * x1
                                + W_ih[rex * 3 + 2] * x2;
                        asm volatile("st.global.cg.f32 [%0], %1;"
                            :: "l"(&gbuf[((rex & 2047) << 2) | (rex >> 11)]), "f"(aex + e) : "memory");
                    }
                }
            }
            asm volatile("bar.sync 3, 320;" ::: "memory");
            if (wid == 0 && lane == 0) {
                __threadfence();
                st_rel(&g_gflag[b * 32], fb + t + 1);
            }
        }
    } else if (wid < 26) {
        // ---- updaters ----
        const int u  = wid - 10;            // 0..15
        const int jb = u * 32 + lane;       // 0..511
        float cst[4] = {0.f, 0.f, 0.f, 0.f};

        for (int t = 0; t < T_; ++t) {
            const unsigned tgt = fb + t + 1;
            if (u < 5) {
                int f = u * 32 + lane;
                if (f < NBLK) {
                    while ((int)(ld_acq(&g_gflag[f * 32]) - tgt) < 0) __nanosleep(64);
                }
            }
            asm volatile("bar.sync 2, 512;" ::: "memory");

            const float* gbuf = g_gates[t];
            float4 q[4];
            #pragma unroll
            for (int c = 0; c < 4; ++c)
                q[c] = ldcg4(gbuf + ((c * 512 + jb) << 2));

            const bool wrb = (b == t);
            #pragma unroll
            for (int c = 0; c < 4; ++c) {
                int j = c * 512 + jb;
                float i_ = fast_sigmoid(q[c].x);
                float f_ = fast_sigmoid(q[c].y);
                float g_ = fast_tanh(q[c].z);
                float o_ = fast_sigmoid(q[c].w);
                cst[c] = fmaf(f_, cst[c], i_ * g_);
                float h = o_ * fast_tanh(cst[c]);
                hsm[j] = h;
                if (wrb) {
                    out_hs[(size_t)t * D_ + j] = h;
                    g_hall[(size_t)t * D_ + j] = h;
                }
                asm volatile("bar.sync 2, 512;" ::: "memory");
                if (u == 0 && lane == 0) sflg[c] = t + 1;
            }
        }
    }
    // warps 26..31 fall through to the structural barrier

    gridbar(++gen);     // all h published

    // =======================================================================
    // D-pass: d[t][v] = Wd[v,:] . h_t  as TC GEMM, K-split 4 partials.
    // =======================================================================
    if (b < 64) {
        __half* sa = (__half*)dynsm;
        __half* sb = sa + 128 * KS;
        const int v0 = (b & 15) * 128;
        const int ksp = b >> 4;
        const int klo = ksp * 512;
        const int warpM = wid >> 3;
        const int warpN = wid & 7;
        const int g  = lane >> 2;
        const int t2 = (lane & 3) * 2;
        const int ldrow = tid >> 3;
        const int ldk   = (tid & 7) * 4;

        float c[2][2][4];
        #pragma unroll
        for (int m = 0; m < 2; ++m)
            #pragma unroll
            for (int n = 0; n < 2; ++n)
                #pragma unroll
                for (int q = 0; q < 4; ++q) c[m][n][q] = 0.f;

        for (int k0 = klo; k0 < klo + 512; k0 += 32) {
            int tt = ldrow; if (tt > 64) tt = 64;
            float4 av = __ldcg((const float4*)&g_hall[(size_t)tt * D_ + k0 + ldk]);
            uint2  bv = __ldcg((const uint2*)&g_w16[(size_t)(LEFT + v0 + ldrow) * D_ + k0 + ldk]);
            __syncthreads();
            *(__half2*)&sa[ldrow * KS + ldk]     = __floats2half2_rn(av.x, av.y);
            *(__half2*)&sa[ldrow * KS + ldk + 2] = __floats2half2_rn(av.z, av.w);
            *(uint2*)&sb[ldrow * KS + ldk] = bv;
            __syncthreads();

            #pragma unroll
            for (int ks = 0; ks < 2; ++ks) {
                const int kb = ks * 16;
                unsigned a[2][4], bb[2][2];
                #pragma unroll
                for (int m = 0; m < 2; ++m) {
                    int ar = warpM * 32 + m * 16;
                    a[m][0] = *(const unsigned*)&sa[(ar + g) * KS + kb + t2];
                    a[m][1] = *(const unsigned*)&sa[(ar + g + 8) * KS + kb + t2];
                    a[m][2] = *(const unsigned*)&sa[(ar + g) * KS + kb + t2 + 8];
                    a[m][3] = *(const unsigned*)&sa[(ar + g + 8) * KS + kb + t2 + 8];
                }
                #pragma unroll
                for (int n = 0; n < 2; ++n) {
                    int br = warpN * 16 + n * 8;
                    bb[n][0] = *(const unsigned*)&sb[(br + g) * KS + kb + t2];
                    bb[n][1] = *(const unsigned*)&sb[(br + g) * KS + kb + t2 + 8];
                }
                #pragma unroll
                for (int m = 0; m < 2; ++m)
                    #pragma unroll
                    for (int n = 0; n < 2; ++n)
                        mma16816(c[m][n], a[m], bb[n]);
            }
        }

        float* dp = g_dp[ksp];
        #pragma unroll
        for (int m = 0; m < 2; ++m) {
            #pragma unroll
            for (int n = 0; n < 2; ++n) {
                int trow = warpM * 32 + m * 16 + g;
                int vcol = v0 + warpN * 16 + n * 8 + t2;
                if (trow < T_) {
                    dp[(size_t)trow * V_ + vcol]     = c[m][n][0];
                    dp[(size_t)trow * V_ + vcol + 1] = c[m][n][1];
                }
                if (trow + 8 < T_) {
                    dp[(size_t)(trow + 8) * V_ + vcol]     = c[m][n][2];
                    dp[(size_t)(trow + 8) * V_ + vcol + 1] = c[m][n][3];
                }
            }
        }
    }

    gridbar(++gen);

    // =======================================================================
    // Stage 2: logits[t][l] = sum_v tanh(enc[l][v] + d_t[v]) * v_w[v] + v_b
    // =======================================================================
    float* sd  = (float*)dynsm;
    float* svw = (float*)(dynsm + D_ * 4);
    for (int j = tid; j < V_; j += NT) svw[j] = v_w[j];
    const float vb = v_b[0];

    for (int item = b; item < T_ * 9; item += NBLK) {
        const int t  = item / 9;
        const int ch = item % 9;
        __syncthreads();
        for (int j = tid; j < V_; j += NT) {
            float d = __ldcg(&g_dp[0][(size_t)t * V_ + j])
                    + __ldcg(&g_dp[1][(size_t)t * V_ + j])
                    + __ldcg(&g_dp[2][(size_t)t * V_ + j])
                    + __ldcg(&g_dp[3][(size_t)t * V_ + j])
                    + Wd_b[j];
            sd[j] = d;
        }
        __syncthreads();

        const int lbase = ch * 57;
        const float4* d4 = (const float4*)sd;
        const float4* w4 = (const float4*)svw;
        for (int l = lbase + wid; l < lbase + 57; l += NW) {
            const float4* e4 = (const float4*)(g_enc + (size_t)l * V_);
            float acc = 0.f;
            #pragma unroll 2
            for (int k = lane; k < V_ / 4; k += 32) {
                float4 e = __ldcg(e4 + k);
                float4 d = d4[k];
                float4 w = w4[k];
                acc = fmaf(hw_tanh(e.x + d.x), w.x, acc);
                acc = fmaf(hw_tanh(e.y + d.y), w.y, acc);
                acc = fmaf(hw_tanh(e.z + d.z), w.z, acc);
                acc = fmaf(hw_tanh(e.w + d.w), w.w, acc);
            }
            #pragma unroll
            for (int off = 16; off > 0; off >>= 1)
                acc += __shfl_down_sync(0xffffffffu, acc, off);
            if (lane == 0) __stcg(&out_logits[(size_t)t * LP1 + l], acc + vb);
        }
    }

    gridbar(++gen);

    // =======================================================================
    // Stage 3: losses
    // =======================================================================
    if (b < T_) {
        const int t = b;
        const float* lg = out_logits + (size_t)t * LP1;

        float m = -1e30f;
        for (int i = tid; i < LP1; i += NT) m = fmaxf(m, __ldcg(lg + i));
        #pragma unroll
        for (int off = 16; off > 0; off >>= 1)
            m = fmaxf(m, __shfl_down_sync(0xffffffffu, m, off));
        if (lane == 0) red[wid] = m;
        __syncthreads();
        if (wid == 0) {
            float mm = (lane < NW) ? red[lane] : -1e30f;
            #pragma unroll
            for (int off = 16; off > 0; off >>= 1)
                mm = fmaxf(mm, __shfl_down_sync(0xffffffffu, mm, off));
            if (lane == 0) red[0] = mm;
        }
        __syncthreads();
        m = red[0];
        __syncthreads();

        float s = 0.f;
        for (int i = tid; i < LP1; i += NT) s += expf(__ldcg(lg + i) - m);
        #pragma unroll
        for (int off = 16; off > 0; off >>= 1)
            s += __shfl_down_sync(0xffffffffu, s, off);
        if (lane == 0) red[wid] = s;
        __syncthreads();
        if (wid == 0) {
            float ss = (lane < NW) ? red[lane] : 0.f;
            #pragma unroll
            for (int off = 16; off > 0; off >>= 1)
                ss += __shfl_down_sync(0xffffffffu, ss, off);
            if (lane == 0) {
                int tgt = (t < 64) ? positions[t] : LSEQ;
                out_losses[t] = m + logf(ss) - __ldcg(lg + tgt);
            }
        }
    }
}

// ---------------------------------------------------------------------------
extern "C" void kernel_launch(void* const* d_in, const int* in_sizes, int n_in,
                              void* d_out, int out_size) {
    const float* initial_state = (const float*)d_in[0];
    const float* enc_states    = (const float*)d_in[1];
    const float* seq_points    = (const float*)d_in[2];
    const int*   positions     = (const int*)  d_in[3];
    const float* W_ih          = (const float*)d_in[4];
    const float* W_hh          = (const float*)d_in[5];
    const float* b_ih          = (const float*)d_in[6];
    const float* b_hh          = (const float*)d_in[7];
    const float* We_w          = (const float*)d_in[8];
    const float* We_b          = (const float*)d_in[9];
    const float* Wd_w          = (const float*)d_in[10];
    const float* Wd_b          = (const float*)d_in[11];
    const float* v_w           = (const float*)d_in[12];
    const float* v_b           = (const float*)d_in[13];

    float* out        = (float*)d_out;
    float* out_logits = out;
    float* out_hs     = out + T_ * LP1;
    float* out_losses = out + T_ * LP1 + T_ * D_;

    static int smem_set = 0;
    if (!smem_set) {
        cudaFuncSetAttribute(decoder_kernel,
                             cudaFuncAttributeMaxDynamicSharedMemorySize, SMEM_BYTES);
        smem_set = 1;
    }

    decoder_kernel<<<NBLK, NT, SMEM_BYTES>>>(
        initial_state, enc_states, seq_points, positions,
        W_ih, W_hh, b_ih, b_hh, We_w, We_b, Wd_w, Wd_b,
        v_w, v_b, out_logits, out_hs, out_losses);
}

// round 9
// speedup vs baseline: 1.1389x; 1.0017x over previous
#include <cuda_runtime.h>
#include <cuda_fp16.h>
#include <math.h>

// ---------------------------------------------------------------------------
#define D_    2048
#define V_    2048
#define LSEQ  512
#define LP1   513
#define T_    65
#define G4    8192

#define NBLK  148
#define NT    1024
#define NW    32

#define JSM   13              // SMEM-resident h-elements per block (148*13 = 1924)
#define JL0   1924            // leftover j's 1924..2047 -> blocks 0..123 (L2 fp16)
#define NJX   124

#define CANARY 0x7FC0DEADu    // NaN payload: h = o*tanh(c) can never be NaN

// dynamic smem layout (bytes)
#define OFF_W    0                            // 13*4 rows * 2048 halves = 212992
#define OFF_H    (JSM * 4 * D_ * 2)           // 212992: h[2048] f32
#define OFF_PP   (OFF_H + D_ * 4)             // 221184: row params 14*4*4 f32 = 896
#define OFF_XS   (OFF_PP + 896)               // 222080: xs[65][4] f32 = 1040
#define OFF_RED  (OFF_XS + 1040)              // 223120: red[32]
#define SMEM_BYTES (OFF_RED + 144)            // 223264

// ---------------------------------------------------------------------------
__device__ __half g_w16[(size_t)V_ * D_];        // fp16 Wd rows (8 MB)
__device__ __half g_w16x[(size_t)NJX * 4 * D_];  // fp16 leftover gate rows (2 MB)
__device__ float g_enc[LP1 * V_];                // enc_proj
__device__ float g_hall[T_ * D_];                // h_t (poisoned, data-flow sync)
__device__ float g_dp[4][T_ * V_];               // K-split partial d
__device__ volatile unsigned g_arr[256];         // structural barrier slots
__device__ volatile unsigned g_rel;              // structural barrier release flag

// ---------------------------------------------------------------------------
// Structural grid barrier (4x per launch)
// ---------------------------------------------------------------------------
__device__ __forceinline__ void gridbar(unsigned gen) {
    __syncthreads();
    const int tid = threadIdx.x;
    if (tid == 0)
        asm volatile("st.release.gpu.global.u32 [%0], %1;"
                     :: "l"((void*)&g_arr[blockIdx.x]), "r"(gen) : "memory");
    if (blockIdx.x == 0) {
        if (tid < NBLK) {
            unsigned v;
            do {
                asm volatile("ld.acquire.gpu.global.u32 %0, [%1];"
                             : "=r"(v) : "l"((const void*)&g_arr[tid]) : "memory");
            } while ((int)(v - gen) < 0);
        }
        __syncthreads();
        if (tid == 0)
            asm volatile("st.release.gpu.global.u32 [%0], %1;"
                         :: "l"((void*)&g_rel), "r"(gen) : "memory");
    } else {
        if (tid == 0) {
            unsigned v;
            do {
                asm volatile("ld.acquire.gpu.global.u32 %0, [%1];"
                             : "=r"(v) : "l"((const void*)&g_rel) : "memory");
            } while ((int)(v - gen) < 0);
        }
        __syncthreads();
    }
}

// ---------------------------------------------------------------------------
// Branchless rational tanh (Eigen 13/6) + Newton reciprocal (no MUFU).
// ---------------------------------------------------------------------------
__device__ __forceinline__ float fast_tanh(float x) {
    float xc = fminf(fmaxf(x, -7.90531110763549805f), 7.90531110763549805f);
    float x2 = xc * xc;
    float p = -2.76076847742355e-16f;
    p = fmaf(p, x2, 2.00018790482477e-13f);
    p = fmaf(p, x2, -8.60467152213735e-11f);
    p = fmaf(p, x2, 5.12229709037114e-08f);
    p = fmaf(p, x2, 1.48572235717979e-05f);
    p = fmaf(p, x2, 6.37261928875436e-04f);
    p = fmaf(p, x2, 4.89352455891786e-03f);
    p *= xc;
    float q = 1.19825839466702e-06f;
    q = fmaf(q, x2, 1.18534705686654e-04f);
    q = fmaf(q, x2, 2.26843463243900e-03f);
    q = fmaf(q, x2, 4.89352518554385e-03f);
    float r = __uint_as_float(0x7EF311C3u - __float_as_uint(q));
    r = r * fmaf(-q, r, 2.0f);
    r = r * fmaf(-q, r, 2.0f);
    r = r * fmaf(-q, r, 2.0f);
    return p * r;
}
__device__ __forceinline__ float hw_tanh(float x) {
    float y;
    asm("tanh.approx.f32 %0, %1;" : "=f"(y) : "f"(x));
    return y;
}

// fp16 dot8
__device__ __forceinline__ float dot8(uint4 u, float4 ha, float4 hb, float acc) {
    float2 f0 = __half22float2(*(__half2*)&u.x);
    float2 f1 = __half22float2(*(__half2*)&u.y);
    float2 f2 = __half22float2(*(__half2*)&u.z);
    float2 f3 = __half22float2(*(__half2*)&u.w);
    acc = fmaf(f0.x, ha.x, acc);
    acc = fmaf(f0.y, ha.y, acc);
    acc = fmaf(f1.x, ha.z, acc);
    acc = fmaf(f1.y, ha.w, acc);
    acc = fmaf(f2.x, hb.x, acc);
    acc = fmaf(f2.y, hb.y, acc);
    acc = fmaf(f3.x, hb.z, acc);
    acc = fmaf(f3.y, hb.w, acc);
    return acc;
}

// mma.sync m16n8k16 row.col f32.f16.f16.f32
__device__ __forceinline__ void mma16816(float* c, const unsigned* a, const unsigned* b) {
    asm volatile(
        "mma.sync.aligned.m16n8k16.row.col.f32.f16.f16.f32 "
        "{%0,%1,%2,%3}, {%4,%5,%6,%7}, {%8,%9}, {%0,%1,%2,%3};"
        : "+f"(c[0]), "+f"(c[1]), "+f"(c[2]), "+f"(c[3])
        : "r"(a[0]), "r"(a[1]), "r"(a[2]), "r"(a[3]), "r"(b[0]), "r"(b[1]));
}

#define KS 40

__global__ void __launch_bounds__(NT, 1)
decoder_kernel(const float* __restrict__ initial_state,
               const float* __restrict__ enc_states,
               const float* __restrict__ seq_points,
               const int*   __restrict__ positions,
               const float* __restrict__ W_ih,
               const float* __restrict__ W_hh,
               const float* __restrict__ b_ih,
               const float* __restrict__ b_hh,
               const float* __restrict__ We_w,
               const float* __restrict__ We_b,
               const float* __restrict__ Wd_w,
               const float* __restrict__ Wd_b,
               const float* __restrict__ v_w,
               const float* __restrict__ v_b,
               float* __restrict__ out_logits,
               float* __restrict__ out_hs,
               float* __restrict__ out_losses)
{
    extern __shared__ __align__(16) char dynsm[];
    __half* wsm = (__half*)dynsm;
    float*  hsm = (float*)(dynsm + OFF_H);
    float*  pp  = (float*)(dynsm + OFF_PP);
    float*  xs  = (float*)(dynsm + OFF_XS);
    float*  red = (float*)(dynsm + OFF_RED);

    const int tid  = threadIdx.x;
    const int wid  = tid >> 5;
    const int lane = tid & 31;
    const int b    = blockIdx.x;

    unsigned gen = g_rel;     // structural-barrier epoch base

    // =======================================================================
    // Phase G: enc_proj GEMM on tensor cores (blocks 0..79)
    // =======================================================================
    if (b < 80) {
        __half* ga = (__half*)dynsm;
        __half* gb = ga + 128 * KS;
        const int l0 = (b / 16) * 128;
        const int v0 = (b % 16) * 128;
        const int warpM = wid >> 3;
        const int warpN = wid & 7;
        const int g  = lane >> 2;
        const int t2 = (lane & 3) * 2;
        const int ldrow = tid >> 3;
        const int ldk   = (tid & 7) * 4;

        float c[2][2][4];
        #pragma unroll
        for (int m = 0; m < 2; ++m)
            #pragma unroll
            for (int n = 0; n < 2; ++n)
                #pragma unroll
                for (int q = 0; q < 4; ++q) c[m][n][q] = 0.f;

        for (int k0 = 0; k0 < D_; k0 += 32) {
            int gl = l0 + ldrow; if (gl > 512) gl = 512;
            float4 av = *(const float4*)&enc_states[(size_t)gl * D_ + k0 + ldk];
            float4 bv = *(const float4*)&We_w[(size_t)(v0 + ldrow) * D_ + k0 + ldk];
            __syncthreads();
            *(__half2*)&ga[ldrow * KS + ldk]     = __floats2half2_rn(av.x, av.y);
            *(__half2*)&ga[ldrow * KS + ldk + 2] = __floats2half2_rn(av.z, av.w);
            *(__half2*)&gb[ldrow * KS + ldk]     = __floats2half2_rn(bv.x, bv.y);
            *(__half2*)&gb[ldrow * KS + ldk + 2] = __floats2half2_rn(bv.z, bv.w);
            __syncthreads();

            #pragma unroll
            for (int ks = 0; ks < 2; ++ks) {
                const int kb = ks * 16;
                unsigned a[2][4], bb[2][2];
                #pragma unroll
                for (int m = 0; m < 2; ++m) {
                    int ar = warpM * 32 + m * 16;
                    a[m][0] = *(const unsigned*)&ga[(ar + g) * KS + kb + t2];
                    a[m][1] = *(const unsigned*)&ga[(ar + g + 8) * KS + kb + t2];
                    a[m][2] = *(const unsigned*)&ga[(ar + g) * KS + kb + t2 + 8];
                    a[m][3] = *(const unsigned*)&ga[(ar + g + 8) * KS + kb + t2 + 8];
                }
                #pragma unroll
                for (int n = 0; n < 2; ++n) {
                    int br = warpN * 16 + n * 8;
                    bb[n][0] = *(const unsigned*)&gb[(br + g) * KS + kb + t2];
                    bb[n][1] = *(const unsigned*)&gb[(br + g) * KS + kb + t2 + 8];
                }
                #pragma unroll
                for (int m = 0; m < 2; ++m)
                    #pragma unroll
                    for (int n = 0; n < 2; ++n)
                        mma16816(c[m][n], a[m], bb[n]);
            }
        }

        #pragma unroll
        for (int m = 0; m < 2; ++m) {
            #pragma unroll
            for (int n = 0; n < 2; ++n) {
                int lrow = l0 + warpM * 32 + m * 16 + g;
                int vcol = v0 + warpN * 16 + n * 8 + t2;
                if (lrow < LP1) {
                    g_enc[(size_t)lrow * V_ + vcol]     = c[m][n][0] + We_b[vcol];
                    g_enc[(size_t)lrow * V_ + vcol + 1] = c[m][n][1] + We_b[vcol + 1];
                }
                if (lrow + 8 < LP1) {
                    g_enc[(size_t)(lrow + 8) * V_ + vcol]     = c[m][n][2] + We_b[vcol];
                    g_enc[(size_t)(lrow + 8) * V_ + vcol + 1] = c[m][n][3] + We_b[vcol + 1];
                }
            }
        }
        __syncthreads();
    }

    // =======================================================================
    // Prologue A (all blocks): own 52 gate rows -> SMEM fp16.
    // Row rr = lj*4+gate corresponds to W_hh row  gate*2048 + b*13 + lj.
    // =======================================================================
    {
        const int n4 = JSM * 4 * (D_ / 4);          // 26624 float4s
        for (int i = tid; i < n4; i += NT) {
            int rr = i >> 9;                        // 0..51
            int k4 = i & 511;
            int lj = rr >> 2, gate = rr & 3;
            const float4* src = (const float4*)&W_hh[(size_t)(gate * D_ + b * JSM + lj) * D_] + k4;
            float4 v = *src;
            __half2 h01 = __floats2half2_rn(v.x, v.y);
            __half2 h23 = __floats2half2_rn(v.z, v.w);
            uint2 pk; pk.x = *(unsigned*)&h01; pk.y = *(unsigned*)&h23;
            ((uint2*)wsm)[(size_t)rr * 512 + k4] = pk;
        }
    }
    // row params: B = b_ih+b_hh, Wih[0..2]   (14 j's: 13 SMEM + 1 L2)
    if (tid < 56) {
        int lj = tid >> 2, gate = tid & 3;
        int j = (lj < JSM) ? (b * JSM + lj) : (JL0 + b);
        if (lj < JSM || b < NJX) {
            int r = gate * D_ + j;
            pp[tid * 4 + 0] = b_ih[r] + b_hh[r];
            pp[tid * 4 + 1] = W_ih[r * 3 + 0];
            pp[tid * 4 + 2] = W_ih[r * 3 + 1];
            pp[tid * 4 + 3] = W_ih[r * 3 + 2];
        }
    }
    // teacher-forced inputs
    if (tid < T_) {
        float x0 = 0.f, x1 = 0.f, x2 = 1.f;
        if (tid >= 1) {
            int pos = positions[tid - 1];
            x0 = seq_points[pos * 3 + 0];
            x1 = seq_points[pos * 3 + 1];
            x2 = seq_points[pos * 3 + 2];
        }
        xs[tid * 4 + 0] = x0; xs[tid * 4 + 1] = x1; xs[tid * 4 + 2] = x2;
    }
    // Prologue B (blocks 80..147): Wd + leftover gate rows -> fp16 L2 buffers
    if (b >= 80) {
        const int nWd = V_ * (D_ / 4);              // 1048576
        const int nX  = NJX * 4 * (D_ / 4);         // 253952
        for (int i = (b - 80) * NT + tid; i < nWd + nX; i += (NBLK - 80) * NT) {
            float4 v; uint2* dst;
            if (i < nWd) {
                v = ((const float4*)Wd_w)[i];
                dst = (uint2*)g_w16 + i;
            } else {
                int ii = i - nWd;
                int flat = ii >> 9;                 // (jj*4+gate)
                int k4 = ii & 511;
                int jj = flat >> 2, gate = flat & 3;
                v = *((const float4*)&W_hh[(size_t)(gate * D_ + JL0 + jj) * D_] + k4);
                dst = (uint2*)g_w16x + ii;
            }
            __half2 h01 = __floats2half2_rn(v.x, v.y);
            __half2 h23 = __floats2half2_rn(v.z, v.w);
            uint2 pk; pk.x = *(unsigned*)&h01; pk.y = *(unsigned*)&h23;
            *dst = pk;
        }
    }
    // Prologue C (blocks 0..79): poison h buffers
    if (b < 80) {
        unsigned* hh = (unsigned*)g_hall;
        for (int i = b * NT + tid; i < T_ * D_; i += 80 * NT)
            hh[i] = CANARY;
    }

    // init h state
    hsm[tid]      = initial_state[tid];
    hsm[tid + NT] = initial_state[tid + NT];
    gridbar(++gen);

    // =======================================================================
    // Stage 1: 65 steps, data-flow sync on h values only (one L2 hop/step).
    //   warps 0..5: 2 SMEM j's; warp 6: 1 SMEM j; warp 7: L2 j (b<124).
    // =======================================================================
    {
        const int njs = (wid < 6) ? 2 : ((wid == 6) ? 1 : ((wid == 7 && b < NJX) ? 1 : 0));
        const int lj0 = (wid < 6) ? 2 * wid : ((wid == 6) ? 12 : 13);
        float cst[2] = {0.f, 0.f};

        for (int t = 0; t < T_; ++t) {
            if (njs) {
                const float4* h4 = (const float4*)hsm;
                const float x0 = xs[t * 4 + 0], x1 = xs[t * 4 + 1], x2 = xs[t * 4 + 2];

                #pragma unroll
                for (int jj = 0; jj < 2; ++jj) {
                    if (jj >= njs) break;
                    const int lj = lj0 + jj;
                    float acc[4] = {0.f, 0.f, 0.f, 0.f};

                    if (wid < 7) {
                        const uint4* w0 = (const uint4*)wsm + (size_t)(lj * 4) * 256;
                        #pragma unroll 2
                        for (int k8 = lane; k8 < 256; k8 += 32) {
                            float4 ha = h4[2 * k8];
                            float4 hb = h4[2 * k8 + 1];
                            acc[0] = dot8(w0[k8], ha, hb, acc[0]);
                            acc[1] = dot8(w0[256 + k8], ha, hb, acc[1]);
                            acc[2] = dot8(w0[512 + k8], ha, hb, acc[2]);
                            acc[3] = dot8(w0[768 + k8], ha, hb, acc[3]);
                        }
                    } else {
                        const uint4* w0 = (const uint4*)g_w16x + (size_t)(b * 4) * 256;
                        #pragma unroll 2
                        for (int k8 = lane; k8 < 256; k8 += 32) {
                            float4 ha = h4[2 * k8];
                            float4 hb = h4[2 * k8 + 1];
                            acc[0] = dot8(__ldcg(w0 + k8), ha, hb, acc[0]);
                            acc[1] = dot8(__ldcg(w0 + 256 + k8), ha, hb, acc[1]);
                            acc[2] = dot8(__ldcg(w0 + 512 + k8), ha, hb, acc[2]);
                            acc[3] = dot8(__ldcg(w0 + 768 + k8), ha, hb, acc[3]);
                        }
                    }
                    // butterfly: all lanes get all 4 sums
                    #pragma unroll
                    for (int off = 16; off > 0; off >>= 1) {
                        acc[0] += __shfl_xor_sync(0xffffffffu, acc[0], off);
                        acc[1] += __shfl_xor_sync(0xffffffffu, acc[1], off);
                        acc[2] += __shfl_xor_sync(0xffffffffu, acc[2], off);
                        acc[3] += __shfl_xor_sync(0xffffffffu, acc[3], off);
                    }
                    // lanes 0..3 each evaluate one gate activation
                    const int gsel = lane & 3;
                    const float* P = pp + (lj * 4 + gsel) * 4;
                    float e = P[0] + P[1] * x0 + P[2] * x1 + P[3] * x2;
                    float z = ((gsel == 0) ? acc[0] : (gsel == 1) ? acc[1]
                             : (gsel == 2) ? acc[2] : acc[3]) + e;
                    bool isG = (gsel == 2);
                    float arg = isG ? z : 0.5f * z;
                    float yt  = fast_tanh(arg);
                    float y   = isG ? yt : fmaf(0.5f, yt, 0.5f);
                    float i_ = __shfl_sync(0xffffffffu, y, 0);
                    float f_ = __shfl_sync(0xffffffffu, y, 1);
                    float g_ = __shfl_sync(0xffffffffu, y, 2);
                    float o_ = __shfl_sync(0xffffffffu, y, 3);
                    cst[jj] = fmaf(f_, cst[jj], i_ * g_);
                    float h = o_ * fast_tanh(cst[jj]);
                    if (lane == 0) {
                        int jglob = (wid < 7) ? (b * JSM + lj) : (JL0 + b);
                        asm volatile("st.global.cg.f32 [%0], %1;"
                            :: "l"(&g_hall[(size_t)t * D_ + jglob]), "f"(h) : "memory");
                    }
                }
            }
            __syncthreads();      // hsm reads complete before gather overwrites

            // ---- gather h_t: poll own pair directly (value-carried sync) ----
            {
                const float* hb = g_hall + (size_t)t * D_ + 2 * tid;
                unsigned vx, vy;
                asm volatile("ld.global.cg.v2.u32 {%0,%1}, [%2];"
                             : "=r"(vx), "=r"(vy) : "l"(hb) : "memory");
                while (vx == CANARY || vy == CANARY) {
                    __nanosleep(32);
                    asm volatile("ld.global.cg.v2.u32 {%0,%1}, [%2];"
                                 : "=r"(vx), "=r"(vy) : "l"(hb) : "memory");
                }
                float fx = __uint_as_float(vx), fy = __uint_as_float(vy);
                hsm[2 * tid]     = fx;
                hsm[2 * tid + 1] = fy;
                if (b == t) {
                    out_hs[(size_t)t * D_ + 2 * tid]     = fx;
                    out_hs[(size_t)t * D_ + 2 * tid + 1] = fy;
                }
            }
            __syncthreads();      // hsm complete before next matvec
        }
    }

    gridbar(++gen);     // all h published (g_hall fully real-valued)

    // =======================================================================
    // D-pass: d[t][v] = Wd[v,:] . h_t  as TC GEMM, K-split 4 partials.
    // =======================================================================
    if (b < 64) {
        __half* sa = (__half*)dynsm;
        __half* sb = sa + 128 * KS;
        const int v0 = (b & 15) * 128;
        const int ksp = b >> 4;
        const int klo = ksp * 512;
        const int warpM = wid >> 3;
        const int warpN = wid & 7;
        const int g  = lane >> 2;
        const int t2 = (lane & 3) * 2;
        const int ldrow = tid >> 3;
        const int ldk   = (tid & 7) * 4;

        float c[2][2][4];
        #pragma unroll
        for (int m = 0; m < 2; ++m)
            #pragma unroll
            for (int n = 0; n < 2; ++n)
                #pragma unroll
                for (int q = 0; q < 4; ++q) c[m][n][q] = 0.f;

        for (int k0 = klo; k0 < klo + 512; k0 += 32) {
            int tt = ldrow; if (tt > 64) tt = 64;
            float4 av = __ldcg((const float4*)&g_hall[(size_t)tt * D_ + k0 + ldk]);
            uint2  bv = __ldcg((const uint2*)&g_w16[(size_t)(v0 + ldrow) * D_ + k0 + ldk]);
            __syncthreads();
            *(__half2*)&sa[ldrow * KS + ldk]     = __floats2half2_rn(av.x, av.y);
            *(__half2*)&sa[ldrow * KS + ldk + 2] = __floats2half2_rn(av.z, av.w);
            *(uint2*)&sb[ldrow * KS + ldk] = bv;
            __syncthreads();

            #pragma unroll
            for (int ks = 0; ks < 2; ++ks) {
                const int kb = ks * 16;
                unsigned a[2][4], bb[2][2];
                #pragma unroll
                for (int m = 0; m < 2; ++m) {
                    int ar = warpM * 32 + m * 16;
                    a[m][0] = *(const unsigned*)&sa[(ar + g) * KS + kb + t2];
                    a[m][1] = *(const unsigned*)&sa[(ar + g + 8) * KS + kb + t2];
                    a[m][2] = *(const unsigned*)&sa[(ar + g) * KS + kb + t2 + 8];
                    a[m][3] = *(const unsigned*)&sa[(ar + g + 8) * KS + kb + t2 + 8];
                }
                #pragma unroll
                for (int n = 0; n < 2; ++n) {
                    int br = warpN * 16 + n * 8;
                    bb[n][0] = *(const unsigned*)&sb[(br + g) * KS + kb + t2];
                    bb[n][1] = *(const unsigned*)&sb[(br + g) * KS + kb + t2 + 8];
                }
                #pragma unroll
                for (int m = 0; m < 2; ++m)
                    #pragma unroll
                    for (int n = 0; n < 2; ++n)
                        mma16816(c[m][n], a[m], bb[n]);
            }
        }

        float* dp = g_dp[ksp];
        #pragma unroll
        for (int m = 0; m < 2; ++m) {
            #pragma unroll
            for (int n = 0; n < 2; ++n) {
                int trow = warpM * 32 + m * 16 + g;
                int vcol = v0 + warpN * 16 + n * 8 + t2;
                if (trow < T_) {
                    dp[(size_t)trow * V_ + vcol]     = c[m][n][0];
                    dp[(size_t)trow * V_ + vcol + 1] = c[m][n][1];
                }
                if (trow + 8 < T_) {
                    dp[(size_t)(trow + 8) * V_ + vcol]     = c[m][n][2];
                    dp[(size_t)(trow + 8) * V_ + vcol + 1] = c[m][n][3];
                }
            }
        }
    }

    gridbar(++gen);

    // =======================================================================
    // Stage 2: logits[t][l] = sum_v tanh(enc[l][v] + d_t[v]) * v_w[v] + v_b
    // =======================================================================
    float* sd  = (float*)dynsm;
    float* svw = (float*)(dynsm + D_ * 4);
    for (int j = tid; j < V_; j += NT) svw[j] = v_w[j];
    const float vb = v_b[0];

    for (int item = b; item < T_ * 9; item += NBLK) {
        const int t  = item / 9;
        const int ch = item % 9;
        __syncthreads();
        for (int j = tid; j < V_; j += NT) {
            float d = __ldcg(&g_dp[0][(size_t)t * V_ + j])
                    + __ldcg(&g_dp[1][(size_t)t * V_ + j])
                    + __ldcg(&g_dp[2][(size_t)t * V_ + j])
                    + __ldcg(&g_dp[3][(size_t)t * V_ + j])
                    + Wd_b[j];
            sd[j] = d;
        }
        __syncthreads();

        const int lbase = ch * 57;
        const float4* d4 = (const float4*)sd;
        const float4* w4 = (const float4*)svw;
        for (int l = lbase + wid; l < lbase + 57; l += NW) {
            const float4* e4 = (const float4*)(g_enc + (size_t)l * V_);
            float acc = 0.f;
            #pragma unroll 2
            for (int k = lane; k < V_ / 4; k += 32) {
                float4 e = __ldcg(e4 + k);
                float4 d = d4[k];
                float4 w = w4[k];
                acc = fmaf(hw_tanh(e.x + d.x), w.x, acc);
                acc = fmaf(hw_tanh(e.y + d.y), w.y, acc);
                acc = fmaf(hw_tanh(e.z + d.z), w.z, acc);
                acc = fmaf(hw_tanh(e.w + d.w), w.w, acc);
            }
            #pragma unroll
            for (int off = 16; off > 0; off >>= 1)
                acc += __shfl_down_sync(0xffffffffu, acc, off);
            if (lane == 0) __stcg(&out_logits[(size_t)t * LP1 + l], acc + vb);
        }
    }

    gridbar(++gen);

    // =======================================================================
    // Stage 3: losses
    // =======================================================================
    if (b < T_) {
        const int t = b;
        const float* lg = out_logits + (size_t)t * LP1;

        float m = -1e30f;
        for (int i = tid; i < LP1; i += NT) m = fmaxf(m, __ldcg(lg + i));
        #pragma unroll
        for (int off = 16; off > 0; off >>= 1)
            m = fmaxf(m, __shfl_down_sync(0xffffffffu, m, off));
        if (lane == 0) red[wid] = m;
        __syncthreads();
        if (wid == 0) {
            float mm = (lane < NW) ? red[lane] : -1e30f;
            #pragma unroll
            for (int off = 16; off > 0; off >>= 1)
                mm = fmaxf(mm, __shfl_down_sync(0xffffffffu, mm, off));
            if (lane == 0) red[0] = mm;
        }
        __syncthreads();
        m = red[0];
        __syncthreads();

        float s = 0.f;
        for (int i = tid; i < LP1; i += NT) s += expf(__ldcg(lg + i) - m);
        #pragma unroll
        for (int off = 16; off > 0; off >>= 1)
            s += __shfl_down_sync(0xffffffffu, s, off);
        if (lane == 0) red[wid] = s;
        __syncthreads();
        if (wid == 0) {
            float ss = (lane < NW) ? red[lane] : 0.f;
            #pragma unroll
            for (int off = 16; off > 0; off >>= 1)
                ss += __shfl_down_sync(0xffffffffu, ss, off);
            if (lane == 0) {
                int tgt = (t < 64) ? positions[t] : LSEQ;
                out_losses[t] = m + logf(ss) - __ldcg(lg + tgt);
            }
        }
    }
}

// ---------------------------------------------------------------------------
extern "C" void kernel_launch(void* const* d_in, const int* in_sizes, int n_in,
                              void* d_out, int out_size) {
    const float* initial_state = (const float*)d_in[0];
    const float* enc_states    = (const float*)d_in[1];
    const float* seq_points    = (const float*)d_in[2];
    const int*   positions     = (const int*)  d_in[3];
    const float* W_ih          = (const float*)d_in[4];
    const float* W_hh          = (const float*)d_in[5];
    const float* b_ih          = (const float*)d_in[6];
    const float* b_hh          = (const float*)d_in[7];
    const float* We_w          = (const float*)d_in[8];
    const float* We_b          = (const float*)d_in[9];
    const float* Wd_w          = (const float*)d_in[10];
    const float* Wd_b          = (const float*)d_in[11];
    const float* v_w           = (const float*)d_in[12];
    const float* v_b           = (const float*)d_in[13];

    float* out        = (float*)d_out;
    float* out_logits = out;
    float* out_hs     = out + T_ * LP1;
    float* out_losses = out + T_ * LP1 + T_ * D_;

    static int smem_set = 0;
    if (!smem_set) {
        cudaFuncSetAttribute(decoder_kernel,
                             cudaFuncAttributeMaxDynamicSharedMemorySize, SMEM_BYTES);
        smem_set = 1;
    }

    decoder_kernel<<<NBLK, NT, SMEM_BYTES>>>(
        initial_state, enc_states, seq_points, positions,
        W_ih, W_hh, b_ih, b_hh, We_w, We_b, Wd_w, Wd_b,
        v_w, v_b, out_logits, out_hs, out_losses);
}